// round 12
// baseline (speedup 1.0000x reference)
#include <cuda_runtime.h>
#include <math.h>
#include <stdint.h>

// ---------------------------------------------------------------------------
// Problem constants
// ---------------------------------------------------------------------------
#define BB   4      // batch
#define CC   64     // C
#define EE   128    // E = 2C
#define HH   128
#define WWID 128
#define WS_  8
#define STR_ 4
#define NH_  31     // windows per dim
#define NWIN (NH_*NH_)          // 961
#define NWB  (NWIN*BB)          // 3844
#define NTOK (NWB*64)           // 246016 token rows
#define HW   (HH*WWID)          // 16384

// ---------------------------------------------------------------------------
// Scratch (static device globals; no runtime allocation)
// ---------------------------------------------------------------------------
__device__ __align__(16) float g_mid [BB*64*HW];          // conv1 out (NCHW)
__device__ __align__(16) float g_nhwc[BB*HW*EE];           // combined0, NHWC
__device__ __align__(16) float g_qkv [(size_t)NTOK*384];
__device__ __align__(16) float g_o2  [(size_t)NTOK*128];
__device__ __align__(16) float g_att [(size_t)NTOK*128];

// ---------------------------------------------------------------------------
// tf32 helpers
// ---------------------------------------------------------------------------
__device__ __forceinline__ uint32_t f2tf(float f) {
    uint32_t u;
    asm("cvt.rna.tf32.f32 %0, %1;" : "=r"(u) : "f"(f));
    return u;
}

__device__ __forceinline__ void mma_tf32(float* d, const uint32_t* a, const uint32_t* b) {
    asm volatile(
        "mma.sync.aligned.m16n8k8.row.col.f32.tf32.tf32.f32 "
        "{%0,%1,%2,%3}, {%4,%5,%6,%7}, {%8,%9}, {%0,%1,%2,%3};\n"
        : "+f"(d[0]), "+f"(d[1]), "+f"(d[2]), "+f"(d[3])
        : "r"(a[0]), "r"(a[1]), "r"(a[2]), "r"(a[3]), "r"(b[0]), "r"(b[1]));
}

// ---------------------------------------------------------------------------
// Implicit-GEMM tf32 conv (3x3, SAME).  One block = 8x8 pixel tile (M=64),
// 128 threads (4 warps, 16 px each), N = Cout, K = Cin*9.
// FIRST: vf(NCHW,64ic) -> g_mid(NCHW,32oc) + ReLU
// !FIRST: g_mid(NCHW,32ic) -> g_nhwc(NHWC,64oc within branch half)
// Halo [ic][iy*10+ix], plane stride 104 (==8 mod 32 -> conflict-free A frags).
// Weights double-buffered Bs[ic][ocP], ocP==8 mod 32 -> conflict-free B frags.
// ---------------------------------------------------------------------------
template<bool FIRST>
__global__ __launch_bounds__(128)
void conv_mma(const float* __restrict__ vin,
              const float* __restrict__ wm, const float* __restrict__ bm,
              const float* __restrict__ wa, const float* __restrict__ ba)
{
    constexpr int CIN   = FIRST ? 64 : 32;
    constexpr int COUT  = FIRST ? 32 : 64;
    constexpr int COUTP = FIRST ? 40 : 72;
    constexpr int NF    = COUT / 8;
    constexpr int PLANE = 104;
    constexpr int SHWORDS = FIRST ? (CIN * PLANE) : 4352;  // conv2: max(halo 3328, sout 64*68)

    __shared__ uint32_t shbuf[SHWORDS];
    __shared__ uint32_t Bs[2][CIN * COUTP];

    int tid  = threadIdx.x;
    int lane = tid & 31;
    int warp = tid >> 5;
    int g = lane >> 2, c = lane & 3;

    int x0 = blockIdx.x * 8;
    int y0 = blockIdx.y * 8;
    int z  = blockIdx.z;
    int b  = z >> 1, br = z & 1;

    const float* w    = br ? wa : wm;
    const float* bias = br ? ba : bm;

    const float* inB = FIRST ? (vin + (size_t)(b * 128 + br * 64) * HW)
                             : (g_mid + (size_t)(b * 64 + br * 32) * HW);

    // ---- stage halo (10x10 per ic, zero-padded borders) ----
    for (int idx = tid; idx < CIN * 100; idx += 128) {
        int ic = idx / 100;
        int r  = idx - ic * 100;
        int iy = r / 10, ix = r - iy * 10;
        int gy = y0 + iy - 1, gx = x0 + ix - 1;
        float v = 0.f;
        if (gy >= 0 && gy < 128 && gx >= 0 && gx < 128)
            v = inB[(size_t)ic * HW + gy * 128 + gx];
        shbuf[ic * PLANE + iy * 10 + ix] = f2tf(v);
    }

    float acc[NF][4];
#pragma unroll
    for (int nt = 0; nt < NF; nt++)
#pragma unroll
        for (int r = 0; r < 4; r++) acc[nt][r] = 0.f;

#pragma unroll
    for (int pos = 0; pos < 9; pos++) {
        int ky = pos / 3, kx = pos - ky * 3;
        uint32_t* B = Bs[pos & 1];
        for (int idx = tid; idx < CIN * COUT; idx += 128) {
            int oc = idx % COUT, ic = idx / COUT;
            B[ic * COUTP + oc] = f2tf(w[oc * (CIN * 9) + ic * 9 + pos]);
        }
        __syncthreads();

        int abase = (warp * 2 + ky) * 10 + g + kx;
#pragma unroll
        for (int kk = 0; kk < CIN / 8; kk++) {
            int ic0 = kk * 8 + c;
            uint32_t a[4];
            a[0] = shbuf[ic0 * PLANE + abase];
            a[1] = shbuf[ic0 * PLANE + abase + 10];
            a[2] = shbuf[(ic0 + 4) * PLANE + abase];
            a[3] = shbuf[(ic0 + 4) * PLANE + abase + 10];
#pragma unroll
            for (int nt = 0; nt < NF; nt++) {
                uint32_t bb[2];
                bb[0] = B[ic0 * COUTP + nt * 8 + g];
                bb[1] = B[(ic0 + 4) * COUTP + nt * 8 + g];
                mma_tf32(acc[nt], a, bb);
            }
        }
        // double-buffered Bs: next staging targets the other buffer; the
        // buffer being overwritten at pos+2 was last read before sync(pos+1).
        if (pos < 8) { /* no trailing sync needed except implicit via next stage+sync */ }
        __syncthreads();
    }

    if (FIRST) {
        // NCHW + bias + ReLU.  lane g -> consecutive x (coalesced per oc).
        int cb = b * 64 + br * 32;
        int rowA = (y0 + warp * 2) * 128 + x0 + g;
        int rowB = rowA + 128;
#pragma unroll
        for (int nt = 0; nt < NF; nt++) {
            int oc0 = nt * 8 + c * 2;
            float b0 = __ldg(bias + oc0);
            float b1 = __ldg(bias + oc0 + 1);
            g_mid[(size_t)(cb + oc0    ) * HW + rowA] = fmaxf(acc[nt][0] + b0, 0.f);
            g_mid[(size_t)(cb + oc0 + 1) * HW + rowA] = fmaxf(acc[nt][1] + b1, 0.f);
            g_mid[(size_t)(cb + oc0    ) * HW + rowB] = fmaxf(acc[nt][2] + b0, 0.f);
            g_mid[(size_t)(cb + oc0 + 1) * HW + rowB] = fmaxf(acc[nt][3] + b1, 0.f);
        }
    } else {
        // smem transpose (reuse shbuf as sout[64][68]) then coalesced NHWC store.
        __syncthreads();   // all halo reads done before aliasing
        float* sout = reinterpret_cast<float*>(shbuf);
        int pA = warp * 16 + g;
#pragma unroll
        for (int nt = 0; nt < NF; nt++) {
            int oc0 = nt * 8 + c * 2;
            float b0 = __ldg(bias + oc0);
            float b1 = __ldg(bias + oc0 + 1);
            sout[pA * 68 + oc0]           = acc[nt][0] + b0;
            sout[pA * 68 + oc0 + 1]       = acc[nt][1] + b1;
            sout[(pA + 8) * 68 + oc0]     = acc[nt][2] + b0;
            sout[(pA + 8) * 68 + oc0 + 1] = acc[nt][3] + b1;
        }
        __syncthreads();
        // 64 px * 64 oc = 1024 float4s
        for (int f = tid; f < 1024; f += 128) {
            int p = f >> 4, q = f & 15;
            float4 v = make_float4(sout[p * 68 + q * 4],     sout[p * 68 + q * 4 + 1],
                                   sout[p * 68 + q * 4 + 2], sout[p * 68 + q * 4 + 3]);
            int y = y0 + (p >> 3), x = x0 + (p & 7);
            *reinterpret_cast<float4*>(
                g_nhwc + ((size_t)(b * 128 + y) * 128 + x) * 128 + br * 64 + q * 4) = v;
        }
    }
}

// ---------------------------------------------------------------------------
// tf32 tensor-core GEMM: C[M x N] = A[M x 128] * Wt[N x 128]^T + bias.
// ---------------------------------------------------------------------------
template<bool GATHER>
__global__ __launch_bounds__(256)
void gemm_tf32_kernel(const float* __restrict__ A, const float* __restrict__ Wt,
                      const float* __restrict__ bias, float* __restrict__ C, int N)
{
    __shared__ uint32_t As[32][136];
    __shared__ uint32_t Bs[32][136];

    int tid  = threadIdx.x;
    int lane = tid & 31;
    int wid  = tid >> 5;
    int wm = wid & 1;
    int wn = wid >> 1;
    int m0 = blockIdx.y * 128;
    int n0 = blockIdx.x * 128;

    float acc[4][4][4];
#pragma unroll
    for (int mt = 0; mt < 4; mt++)
#pragma unroll
        for (int nt = 0; nt < 4; nt++)
#pragma unroll
            for (int r = 0; r < 4; r++) acc[mt][nt][r] = 0.f;

    int q = tid & 7;
    const float* arow[4];
    const float* brow[4];
    int rowIdx[4];
#pragma unroll
    for (int s = 0; s < 4; s++) {
        int row = (tid >> 3) + 32 * s;
        rowIdx[s] = row;
        if (GATHER) {
            int m  = m0 + row;
            int l  = m & 63;
            int wb = m >> 6;
            int b  = wb & 3;
            int win = wb >> 2;
            int hi = win / 31;
            int wi = win - hi * 31;
            int h  = hi * 4 + (l >> 3);
            int wc = wi * 4 + (l & 7);
            arow[s] = g_nhwc + ((size_t)((b * 128 + h) * 128 + wc)) * 128;
        } else {
            arow[s] = A + (size_t)(m0 + row) * 128;
        }
        brow[s] = Wt + (size_t)(n0 + row) * 128;
    }

    for (int k0 = 0; k0 < 128; k0 += 32) {
        __syncthreads();
#pragma unroll
        for (int s = 0; s < 4; s++) {
#pragma unroll
            for (int c = 0; c < 4; c++) {
                int k = q + 8 * c;
                As[k][rowIdx[s]] = f2tf(arow[s][k0 + k]);
                Bs[k][rowIdx[s]] = f2tf(brow[s][k0 + k]);
            }
        }
        __syncthreads();

#pragma unroll
        for (int kk = 0; kk < 4; kk++) {
            int c = lane & 3;
            int g = lane >> 2;
            uint32_t a[4][4], b[4][2];
#pragma unroll
            for (int mt = 0; mt < 4; mt++) {
                int r = wm * 64 + mt * 16 + g;
                a[mt][0] = As[kk * 8 + c    ][r];
                a[mt][1] = As[kk * 8 + c    ][r + 8];
                a[mt][2] = As[kk * 8 + c + 4][r];
                a[mt][3] = As[kk * 8 + c + 4][r + 8];
            }
#pragma unroll
            for (int nt = 0; nt < 4; nt++) {
                int n = wn * 32 + nt * 8 + g;
                b[nt][0] = Bs[kk * 8 + c    ][n];
                b[nt][1] = Bs[kk * 8 + c + 4][n];
            }
#pragma unroll
            for (int mt = 0; mt < 4; mt++)
#pragma unroll
                for (int nt = 0; nt < 4; nt++)
                    mma_tf32(acc[mt][nt], a[mt], b[nt]);
        }
    }

    int g  = lane >> 2;
    int c2 = (lane & 3) * 2;
#pragma unroll
    for (int mt = 0; mt < 4; mt++) {
        int row = m0 + wm * 64 + mt * 16 + g;
#pragma unroll
        for (int nt = 0; nt < 4; nt++) {
            int col = n0 + wn * 32 + nt * 8 + c2;
            float b0 = __ldg(bias + col);
            float b1 = __ldg(bias + col + 1);
            float2 v0 = make_float2(acc[mt][nt][0] + b0, acc[mt][nt][1] + b1);
            float2 v1 = make_float2(acc[mt][nt][2] + b0, acc[mt][nt][3] + b1);
            *reinterpret_cast<float2*>(C + (size_t)row * N + col)       = v0;
            *reinterpret_cast<float2*>(C + (size_t)(row + 8) * N + col) = v1;
        }
    }
}

// ---------------------------------------------------------------------------
// Attention core (tensor cores, R10 version): one block (128 thr) per
// (window*batch, head).  S = Q K^T (mma tf32), smem-staged softmax, O = P V.
// st[m][l] (pad 68) serves directly as the A-operand layout for the PV mma.
// ---------------------------------------------------------------------------
__global__ __launch_bounds__(128)
void attn_kernel()
{
    __shared__ uint32_t qsT[32][72];
    __shared__ uint32_t ksT[32][72];
    __shared__ uint32_t vs [64][40];
    __shared__ float    st [64][68];
    __shared__ float    smx[128];
    __shared__ float    ssum[128];

    int bx   = blockIdx.x;
    int head = bx & 3;
    int wb   = bx >> 2;
    int rowBase = wb * 64;
    int tid  = threadIdx.x;
    int lane = tid & 31;
    int warp = tid >> 5;
    const float scale = 0.17677669529663687f;  // 1/sqrt(32)

    // ---- load Q,K,V (each thread: one l-row, 16 d's) ----
    {
        int l     = tid & 63;
        int dbase = (tid >> 6) * 16;
        const float* p = g_qkv + (size_t)(rowBase + l) * 384 + head * 32 + dbase;
#pragma unroll
        for (int j4 = 0; j4 < 4; j4++) {
            float4 qv = *reinterpret_cast<const float4*>(p + j4 * 4);
            float4 kv = *reinterpret_cast<const float4*>(p + 128 + j4 * 4);
            float4 vv = *reinterpret_cast<const float4*>(p + 256 + j4 * 4);
            int d = dbase + j4 * 4;
            qsT[d + 0][l] = f2tf(qv.x * scale);
            qsT[d + 1][l] = f2tf(qv.y * scale);
            qsT[d + 2][l] = f2tf(qv.z * scale);
            qsT[d + 3][l] = f2tf(qv.w * scale);
            ksT[d + 0][l] = f2tf(kv.x);
            ksT[d + 1][l] = f2tf(kv.y);
            ksT[d + 2][l] = f2tf(kv.z);
            ksT[d + 3][l] = f2tf(kv.w);
            uint4 vt;
            vt.x = f2tf(vv.x); vt.y = f2tf(vv.y);
            vt.z = f2tf(vv.z); vt.w = f2tf(vv.w);
            *reinterpret_cast<uint4*>(&vs[l][d]) = vt;
        }
    }
    __syncthreads();

    int g = lane >> 2, c = lane & 3;
    int lbase = warp * 16;

    // ---- S = Q K^T : M=64(l), N=64(m), K=32(d); warp: 16 l x 64 m ----
    {
        float sacc[8][4];
#pragma unroll
        for (int nt = 0; nt < 8; nt++)
#pragma unroll
            for (int r = 0; r < 4; r++) sacc[nt][r] = 0.f;

#pragma unroll
        for (int kk = 0; kk < 4; kk++) {
            uint32_t a[4];
            a[0] = qsT[kk * 8 + c    ][lbase + g];
            a[1] = qsT[kk * 8 + c    ][lbase + g + 8];
            a[2] = qsT[kk * 8 + c + 4][lbase + g];
            a[3] = qsT[kk * 8 + c + 4][lbase + g + 8];
#pragma unroll
            for (int nt = 0; nt < 8; nt++) {
                uint32_t b[2];
                b[0] = ksT[kk * 8 + c    ][nt * 8 + g];
                b[1] = ksT[kk * 8 + c + 4][nt * 8 + g];
                mma_tf32(sacc[nt], a, b);
            }
        }
        // store transposed: st[m][l]
#pragma unroll
        for (int nt = 0; nt < 8; nt++) {
            int m = nt * 8 + c * 2;
            st[m    ][lbase + g]     = sacc[nt][0];
            st[m + 1][lbase + g]     = sacc[nt][1];
            st[m    ][lbase + g + 8] = sacc[nt][2];
            st[m + 1][lbase + g + 8] = sacc[nt][3];
        }
    }
    __syncthreads();

    // ---- softmax over m per column l; 2 threads per l (32 m each) ----
    {
        int l     = tid & 63;
        int part  = tid >> 6;
        int mbase = part * 32;
        float mx = -1e30f;
#pragma unroll
        for (int i = 0; i < 32; i++) mx = fmaxf(mx, st[mbase + i][l]);
        smx[part * 64 + l] = mx;
        __syncthreads();
        mx = fmaxf(smx[l], smx[64 + l]);
        float s = 0.f;
        float ev[32];
#pragma unroll
        for (int i = 0; i < 32; i++) {
            float e = __expf(st[mbase + i][l] - mx);
            ev[i] = e;
            s += e;
        }
        ssum[part * 64 + l] = s;
        __syncthreads();
        float inv = 1.f / (ssum[l] + ssum[64 + l]);
#pragma unroll
        for (int i = 0; i < 32; i++)
            st[mbase + i][l] = __uint_as_float(f2tf(ev[i] * inv));
    }
    __syncthreads();

    // ---- O = P V : M=64(l), N=32(d), K=64(m); warp: 16 l x 32 d ----
    {
        float oacc[4][4];
#pragma unroll
        for (int nt = 0; nt < 4; nt++)
#pragma unroll
            for (int r = 0; r < 4; r++) oacc[nt][r] = 0.f;

#pragma unroll
        for (int kk = 0; kk < 8; kk++) {
            uint32_t a[4];
            a[0] = __float_as_uint(st[kk * 8 + c    ][lbase + g]);
            a[1] = __float_as_uint(st[kk * 8 + c    ][lbase + g + 8]);
            a[2] = __float_as_uint(st[kk * 8 + c + 4][lbase + g]);
            a[3] = __float_as_uint(st[kk * 8 + c + 4][lbase + g + 8]);
#pragma unroll
            for (int nt = 0; nt < 4; nt++) {
                uint32_t b[2];
                b[0] = vs[kk * 8 + c    ][nt * 8 + g];
                b[1] = vs[kk * 8 + c + 4][nt * 8 + g];
                mma_tf32(oacc[nt], a, b);
            }
        }
        int c2 = c * 2;
#pragma unroll
        for (int nt = 0; nt < 4; nt++) {
            int d = head * 32 + nt * 8 + c2;
            float2 v0 = make_float2(oacc[nt][0], oacc[nt][1]);
            float2 v1 = make_float2(oacc[nt][2], oacc[nt][3]);
            *reinterpret_cast<float2*>(g_o2 + (size_t)(rowBase + lbase + g) * 128 + d)     = v0;
            *reinterpret_cast<float2*>(g_o2 + (size_t)(rowBase + lbase + g + 8) * 128 + d) = v1;
        }
    }
}

// ---------------------------------------------------------------------------
// Blend (analytic scan) + 1x1 conv (smem-staged) + sigmoid gate + residual.
// ---------------------------------------------------------------------------
__global__ void blend_kernel(const float* __restrict__ fcw, const float* __restrict__ fcb,
                             const float* __restrict__ vf, float* __restrict__ out)
{
    __shared__ float enh[32][129];
    __shared__ float fw [32][65];
    __shared__ float fcs[128][76];
    __shared__ float fbs[64];

    int wc = blockIdx.x;     // 0..3
    int h  = blockIdx.y;     // 0..127
    int b  = blockIdx.z;     // 0..3
    int w0 = wc * 32;
    int tid = threadIdx.x;

    for (int idx = tid; idx < 64 * 128; idx += 256) {
        int c = idx >> 7, e = idx & 127;
        fcs[e][c] = fcw[idx];
    }
    if (tid < 64) fbs[tid] = fcb[tid];

    int hiLo = max(0, (h - 4) >> 2);
    int hiHi = min(NH_ - 1, h >> 2);

    for (int s = 0; s < 16; s++) {
        int idx = tid + s * 256;
        int px = idx >> 7;
        int e  = idx & 127;
        int wpix = w0 + px;
        int wiLo = max(0, (wpix - 4) >> 2);
        int wiHi = min(NH_ - 1, wpix >> 2);

        float val = g_nhwc[((size_t)(b * HH + h) * WWID + wpix) * EE + e];
        for (int hi = hiLo; hi <= hiHi; hi++) {
            int lr = (h - hi * 4) * 8;
            for (int wi = wiLo; wi <= wiHi; wi++) {
                int l = lr + (wpix - wi * 4);
                int row = ((hi * NH_ + wi) * 4 + b) * 64 + l;
                val = val * 0.7f + 0.3f * g_att[(size_t)row * 128 + e];
            }
        }
        enh[px][e] = val;
    }
    __syncthreads();

    {
        int px = tid >> 3;
        int cg = tid & 7;
        float acc[8];
#pragma unroll
        for (int j = 0; j < 8; j++) acc[j] = fbs[cg * 8 + j];
#pragma unroll 4
        for (int e = 0; e < 128; e++) {
            float a = enh[px][e];
            const float4* bp = reinterpret_cast<const float4*>(&fcs[e][cg * 8]);
            float4 b0 = bp[0];
            float4 b1 = bp[1];
            acc[0] += a * b0.x; acc[1] += a * b0.y;
            acc[2] += a * b0.z; acc[3] += a * b0.w;
            acc[4] += a * b1.x; acc[5] += a * b1.y;
            acc[6] += a * b1.z; acc[7] += a * b1.w;
        }
#pragma unroll
        for (int j = 0; j < 8; j++)
            fw[px][cg * 8 + j] = 1.f / (1.f + __expf(-acc[j]));
    }
    __syncthreads();

    for (int s = 0; s < 16; s++) {
        int idx = tid + s * 256;
        int px = idx & 31;
        int ch = idx >> 5;
        size_t off = ((size_t)(b * 128 + ch) * HH + h) * WWID + w0 + px;
        out[off] = enh[px][ch] * fw[px][ch & 63] + vf[off];
    }
}

// ---------------------------------------------------------------------------
// Launch
// ---------------------------------------------------------------------------
extern "C" void kernel_launch(void* const* d_in, const int* in_sizes, int n_in,
                              void* d_out, int out_size)
{
    const float* vf    = (const float*)d_in[0];
    const float* mw1   = (const float*)d_in[1];
    const float* mb1   = (const float*)d_in[2];
    const float* mw2   = (const float*)d_in[3];
    const float* mb2   = (const float*)d_in[4];
    const float* aw1   = (const float*)d_in[5];
    const float* ab1   = (const float*)d_in[6];
    const float* aw2   = (const float*)d_in[7];
    const float* ab2   = (const float*)d_in[8];
    const float* ipw   = (const float*)d_in[9];   // [384,128]
    const float* ipb   = (const float*)d_in[10];
    const float* opw   = (const float*)d_in[11];  // [128,128]
    const float* opb   = (const float*)d_in[12];
    const float* fcw   = (const float*)d_in[13];  // [64,128]
    const float* fcb   = (const float*)d_in[14];
    float* out = (float*)d_out;

    void *pqkv, *po2, *patt;
    cudaGetSymbolAddress(&pqkv, g_qkv);
    cudaGetSymbolAddress(&po2,  g_o2);
    cudaGetSymbolAddress(&patt, g_att);

    // convs: implicit-GEMM tf32 tensor cores, 8x8 px tiles
    conv_mma<true ><<<dim3(16, 16, 8), 128>>>(vf, mw1, mb1, aw1, ab1);
    conv_mma<false><<<dim3(16, 16, 8), 128>>>(nullptr, mw2, mb2, aw2, ab2);

    // QKV: tokens (gathered from NHWC) x [384,128]^T  -> g_qkv
    gemm_tf32_kernel<true><<<dim3(3, NTOK / 128), 256>>>(
        nullptr, ipw, ipb, (float*)pqkv, 384);

    attn_kernel<<<NWB * 4, 128>>>();

    // out-proj: g_o2 [NTOK,128] x [128,128]^T -> g_att
    gemm_tf32_kernel<false><<<dim3(1, NTOK / 128), 256>>>(
        (const float*)po2, opw, opb, (float*)patt, 128);

    blend_kernel<<<dim3(4, HH, BB), 256>>>(fcw, fcb, vf, out);
}

// round 13
// speedup vs baseline: 1.1437x; 1.1437x over previous
#include <cuda_runtime.h>
#include <math.h>
#include <stdint.h>

// ---------------------------------------------------------------------------
// Problem constants
// ---------------------------------------------------------------------------
#define BB   4      // batch
#define CC   64     // C
#define EE   128    // E = 2C
#define HH   128
#define WWID 128
#define WS_  8
#define STR_ 4
#define NH_  31     // windows per dim
#define NWIN (NH_*NH_)          // 961
#define NWB  (NWIN*BB)          // 3844
#define NTOK (NWB*64)           // 246016 token rows
#define HW   (HH*WWID)          // 16384

// ---------------------------------------------------------------------------
// Scratch (static device globals; no runtime allocation)
// ---------------------------------------------------------------------------
__device__ __align__(16) float g_mid [BB*64*HW];          // conv1 out
__device__ __align__(16) float g_nhwc[BB*HW*EE];           // combined0, NHWC
__device__ __align__(16) float g_qkv [(size_t)NTOK*384];
__device__ __align__(16) float g_o2  [(size_t)NTOK*128];
__device__ __align__(16) float g_att [(size_t)NTOK*128];

// ---------------------------------------------------------------------------
// tf32 helpers
// ---------------------------------------------------------------------------
__device__ __forceinline__ uint32_t f2tf(float f) {
    uint32_t u;
    asm("cvt.rna.tf32.f32 %0, %1;" : "=r"(u) : "f"(f));
    return u;
}

__device__ __forceinline__ void mma_tf32(float* d, const uint32_t* a, const uint32_t* b) {
    asm volatile(
        "mma.sync.aligned.m16n8k8.row.col.f32.tf32.tf32.f32 "
        "{%0,%1,%2,%3}, {%4,%5,%6,%7}, {%8,%9}, {%0,%1,%2,%3};\n"
        : "+f"(d[0]), "+f"(d[1]), "+f"(d[2]), "+f"(d[3])
        : "r"(a[0]), "r"(a[1]), "r"(a[2]), "r"(a[3]), "r"(b[0]), "r"(b[1]));
}

// ---------------------------------------------------------------------------
// conv1: 3x3, 64 -> 32 per branch, ReLU.  (scalar — known good)
// ---------------------------------------------------------------------------
__global__ void conv1_kernel(const float* __restrict__ vf,
                             const float* __restrict__ mw1, const float* __restrict__ mb1,
                             const float* __restrict__ aw1, const float* __restrict__ ab1)
{
    int z   = blockIdx.z;            // b*8 + br*4 + ocg
    int b   = z >> 3;
    int br  = (z >> 2) & 1;
    int ocg = z & 3;
    const float* w    = br ? aw1 : mw1;   // [32][64][9]
    const float* bias = br ? ab1 : mb1;
    int ocBase = ocg * 8;
    int x0 = blockIdx.x * 32, y0 = blockIdx.y * 16;
    int tx = threadIdx.x, ty = threadIdx.y;
    int tid = ty * 16 + tx;

    __shared__ float sh[8][18][35];
    __shared__ float wsh[8][8][9];

    float acc[8][2];
#pragma unroll
    for (int o = 0; o < 8; o++) {
        float bv = bias[ocBase + o];
        acc[o][0] = bv; acc[o][1] = bv;
    }

    const float* inBase = vf + (size_t)(b * 128 + br * 64) * HW;

    for (int ic0 = 0; ic0 < 64; ic0 += 8) {
        __syncthreads();
        for (int idx = tid; idx < 8 * 18 * 34; idx += 256) {
            int ic = idx / (18 * 34);
            int r  = idx % (18 * 34);
            int iy = r / 34, ix = r % 34;
            int gy = y0 + iy - 1, gx = x0 + ix - 1;
            float v = 0.f;
            if (gy >= 0 && gy < HH && gx >= 0 && gx < WWID)
                v = inBase[(size_t)(ic0 + ic) * HW + gy * WWID + gx];
            sh[ic][iy][ix] = v;
        }
        for (int idx = tid; idx < 8 * 8 * 9; idx += 256) {
            int o = idx / 72;
            int r = idx % 72;
            int ic = r / 9, k = r % 9;
            wsh[o][ic][k] = w[(ocBase + o) * 576 + (ic0 + ic) * 9 + k];
        }
        __syncthreads();
#pragma unroll
        for (int ic = 0; ic < 8; ic++) {
#pragma unroll
            for (int ky = 0; ky < 3; ky++) {
                float xv[4];
#pragma unroll
                for (int q = 0; q < 4; q++) xv[q] = sh[ic][ty + ky][tx * 2 + q];
#pragma unroll
                for (int kx = 0; kx < 3; kx++) {
#pragma unroll
                    for (int o = 0; o < 8; o++) {
                        float wv = wsh[o][ic][ky * 3 + kx];
                        acc[o][0] += xv[kx]     * wv;
                        acc[o][1] += xv[kx + 1] * wv;
                    }
                }
            }
        }
    }
    int y = y0 + ty, x = x0 + tx * 2;
#pragma unroll
    for (int o = 0; o < 8; o++) {
        float* p = g_mid + (size_t)(b * 64 + br * 32 + ocBase + o) * HW + y * WWID + x;
        p[0] = fmaxf(acc[o][0], 0.f);
        p[1] = fmaxf(acc[o][1], 0.f);
    }
}

// ---------------------------------------------------------------------------
// conv2: 3x3, 32 -> 64 per branch, no ReLU, writes NHWC combined0. (scalar)
// ---------------------------------------------------------------------------
__global__ void conv2_kernel(const float* __restrict__ mw2, const float* __restrict__ mb2,
                             const float* __restrict__ aw2, const float* __restrict__ ab2)
{
    int z   = blockIdx.z;            // b*16 + br*8 + ocg
    int b   = z >> 4;
    int br  = (z >> 3) & 1;
    int ocg = z & 7;
    const float* w    = br ? aw2 : mw2;   // [64][32][9]
    const float* bias = br ? ab2 : mb2;
    int ocBase = ocg * 8;
    int x0 = blockIdx.x * 32, y0 = blockIdx.y * 16;
    int tx = threadIdx.x, ty = threadIdx.y;
    int tid = ty * 16 + tx;

    __shared__ float sh[8][18][35];
    __shared__ float wsh[8][8][9];

    float acc[8][2];
#pragma unroll
    for (int o = 0; o < 8; o++) {
        float bv = bias[ocBase + o];
        acc[o][0] = bv; acc[o][1] = bv;
    }

    const float* inBase = g_mid + (size_t)(b * 64 + br * 32) * HW;

    for (int ic0 = 0; ic0 < 32; ic0 += 8) {
        __syncthreads();
        for (int idx = tid; idx < 8 * 18 * 34; idx += 256) {
            int ic = idx / (18 * 34);
            int r  = idx % (18 * 34);
            int iy = r / 34, ix = r % 34;
            int gy = y0 + iy - 1, gx = x0 + ix - 1;
            float v = 0.f;
            if (gy >= 0 && gy < HH && gx >= 0 && gx < WWID)
                v = inBase[(size_t)(ic0 + ic) * HW + gy * WWID + gx];
            sh[ic][iy][ix] = v;
        }
        for (int idx = tid; idx < 8 * 8 * 9; idx += 256) {
            int o = idx / 72;
            int r = idx % 72;
            int ic = r / 9, k = r % 9;
            wsh[o][ic][k] = w[(ocBase + o) * 288 + (ic0 + ic) * 9 + k];
        }
        __syncthreads();
#pragma unroll
        for (int ic = 0; ic < 8; ic++) {
#pragma unroll
            for (int ky = 0; ky < 3; ky++) {
                float xv[4];
#pragma unroll
                for (int q = 0; q < 4; q++) xv[q] = sh[ic][ty + ky][tx * 2 + q];
#pragma unroll
                for (int kx = 0; kx < 3; kx++) {
#pragma unroll
                    for (int o = 0; o < 8; o++) {
                        float wv = wsh[o][ic][ky * 3 + kx];
                        acc[o][0] += xv[kx]     * wv;
                        acc[o][1] += xv[kx + 1] * wv;
                    }
                }
            }
        }
    }
    int y = y0 + ty, x = x0 + tx * 2;
    int e0 = br * 64 + ocBase;
#pragma unroll
    for (int px = 0; px < 2; px++) {
        float4 f0 = make_float4(acc[0][px], acc[1][px], acc[2][px], acc[3][px]);
        float4 f1 = make_float4(acc[4][px], acc[5][px], acc[6][px], acc[7][px]);
        float* p = g_nhwc + ((size_t)(b * HH + y) * WWID + (x + px)) * EE + e0;
        reinterpret_cast<float4*>(p)[0] = f0;
        reinterpret_cast<float4*>(p)[1] = f1;
    }
}

// ---------------------------------------------------------------------------
// tf32 tensor-core GEMM: C[M x N] = A[M x 128] * Wt[N x 128]^T + bias.
// ---------------------------------------------------------------------------
template<bool GATHER>
__global__ __launch_bounds__(256)
void gemm_tf32_kernel(const float* __restrict__ A, const float* __restrict__ Wt,
                      const float* __restrict__ bias, float* __restrict__ C, int N)
{
    __shared__ uint32_t As[32][136];
    __shared__ uint32_t Bs[32][136];

    int tid  = threadIdx.x;
    int lane = tid & 31;
    int wid  = tid >> 5;
    int wm = wid & 1;
    int wn = wid >> 1;
    int m0 = blockIdx.y * 128;
    int n0 = blockIdx.x * 128;

    float acc[4][4][4];
#pragma unroll
    for (int mt = 0; mt < 4; mt++)
#pragma unroll
        for (int nt = 0; nt < 4; nt++)
#pragma unroll
            for (int r = 0; r < 4; r++) acc[mt][nt][r] = 0.f;

    int q = tid & 7;
    const float* arow[4];
    const float* brow[4];
    int rowIdx[4];
#pragma unroll
    for (int s = 0; s < 4; s++) {
        int row = (tid >> 3) + 32 * s;
        rowIdx[s] = row;
        if (GATHER) {
            int m  = m0 + row;
            int l  = m & 63;
            int wb = m >> 6;
            int b  = wb & 3;
            int win = wb >> 2;
            int hi = win / 31;
            int wi = win - hi * 31;
            int h  = hi * 4 + (l >> 3);
            int wc = wi * 4 + (l & 7);
            arow[s] = g_nhwc + ((size_t)((b * 128 + h) * 128 + wc)) * 128;
        } else {
            arow[s] = A + (size_t)(m0 + row) * 128;
        }
        brow[s] = Wt + (size_t)(n0 + row) * 128;
    }

    for (int k0 = 0; k0 < 128; k0 += 32) {
        __syncthreads();
#pragma unroll
        for (int s = 0; s < 4; s++) {
#pragma unroll
            for (int c = 0; c < 4; c++) {
                int k = q + 8 * c;
                As[k][rowIdx[s]] = f2tf(arow[s][k0 + k]);
                Bs[k][rowIdx[s]] = f2tf(brow[s][k0 + k]);
            }
        }
        __syncthreads();

#pragma unroll
        for (int kk = 0; kk < 4; kk++) {
            int c = lane & 3;
            int g = lane >> 2;
            uint32_t a[4][4], b[4][2];
#pragma unroll
            for (int mt = 0; mt < 4; mt++) {
                int r = wm * 64 + mt * 16 + g;
                a[mt][0] = As[kk * 8 + c    ][r];
                a[mt][1] = As[kk * 8 + c    ][r + 8];
                a[mt][2] = As[kk * 8 + c + 4][r];
                a[mt][3] = As[kk * 8 + c + 4][r + 8];
            }
#pragma unroll
            for (int nt = 0; nt < 4; nt++) {
                int n = wn * 32 + nt * 8 + g;
                b[nt][0] = Bs[kk * 8 + c    ][n];
                b[nt][1] = Bs[kk * 8 + c + 4][n];
            }
#pragma unroll
            for (int mt = 0; mt < 4; mt++)
#pragma unroll
                for (int nt = 0; nt < 4; nt++)
                    mma_tf32(acc[mt][nt], a[mt], b[nt]);
        }
    }

    int g  = lane >> 2;
    int c2 = (lane & 3) * 2;
#pragma unroll
    for (int mt = 0; mt < 4; mt++) {
        int row = m0 + wm * 64 + mt * 16 + g;
#pragma unroll
        for (int nt = 0; nt < 4; nt++) {
            int col = n0 + wn * 32 + nt * 8 + c2;
            float b0 = __ldg(bias + col);
            float b1 = __ldg(bias + col + 1);
            float2 v0 = make_float2(acc[mt][nt][0] + b0, acc[mt][nt][1] + b1);
            float2 v1 = make_float2(acc[mt][nt][2] + b0, acc[mt][nt][3] + b1);
            *reinterpret_cast<float2*>(C + (size_t)row * N + col)       = v0;
            *reinterpret_cast<float2*>(C + (size_t)(row + 8) * N + col) = v1;
        }
    }
}

// ---------------------------------------------------------------------------
// Attention core (tensor cores, coalesced I/O): one block (128 thr) per
// (window*batch, head).  Coalesced loads: 8 consecutive lanes read one token
// row's 32-float head slice (128 B contiguous).  O staged in smem, then
// written with the same coalesced pattern.
// qsT/ksT padded to 73 (transposed STS conflict-free; frag LDS <=2-way).
// ---------------------------------------------------------------------------
__global__ __launch_bounds__(128)
void attn_kernel()
{
    __shared__ uint32_t qsT[32][73];
    __shared__ uint32_t ksT[32][73];
    __shared__ uint32_t vs [64][40];
    __shared__ float    st [64][68];
    __shared__ float    smx[128];
    __shared__ float    ssum[128];

    int bx   = blockIdx.x;
    int head = bx & 3;
    int wb   = bx >> 2;
    int rowBase = wb * 64;
    int tid  = threadIdx.x;
    int lane = tid & 31;
    int warp = tid >> 5;
    const float scale = 0.17677669529663687f;  // 1/sqrt(32)

    // ---- coalesced load Q,K,V: idx = row*8 + d4; 8 lanes = 128 B contig ----
#pragma unroll
    for (int s = 0; s < 4; s++) {
        int idx = tid + s * 128;
        int row = idx >> 3;
        int d   = (idx & 7) * 4;
        const float* p = g_qkv + (size_t)(rowBase + row) * 384 + head * 32 + d;
        float4 qv = *reinterpret_cast<const float4*>(p);
        float4 kv = *reinterpret_cast<const float4*>(p + 128);
        float4 vv = *reinterpret_cast<const float4*>(p + 256);
        qsT[d + 0][row] = f2tf(qv.x * scale);
        qsT[d + 1][row] = f2tf(qv.y * scale);
        qsT[d + 2][row] = f2tf(qv.z * scale);
        qsT[d + 3][row] = f2tf(qv.w * scale);
        ksT[d + 0][row] = f2tf(kv.x);
        ksT[d + 1][row] = f2tf(kv.y);
        ksT[d + 2][row] = f2tf(kv.z);
        ksT[d + 3][row] = f2tf(kv.w);
        uint4 vt;
        vt.x = f2tf(vv.x); vt.y = f2tf(vv.y);
        vt.z = f2tf(vv.z); vt.w = f2tf(vv.w);
        *reinterpret_cast<uint4*>(&vs[row][d]) = vt;
    }
    __syncthreads();

    int g = lane >> 2, c = lane & 3;
    int lbase = warp * 16;

    // ---- S = Q K^T : M=64(l), N=64(m), K=32(d); warp: 16 l x 64 m ----
    {
        float sacc[8][4];
#pragma unroll
        for (int nt = 0; nt < 8; nt++)
#pragma unroll
            for (int r = 0; r < 4; r++) sacc[nt][r] = 0.f;

#pragma unroll
        for (int kk = 0; kk < 4; kk++) {
            uint32_t a[4];
            a[0] = qsT[kk * 8 + c    ][lbase + g];
            a[1] = qsT[kk * 8 + c    ][lbase + g + 8];
            a[2] = qsT[kk * 8 + c + 4][lbase + g];
            a[3] = qsT[kk * 8 + c + 4][lbase + g + 8];
#pragma unroll
            for (int nt = 0; nt < 8; nt++) {
                uint32_t b[2];
                b[0] = ksT[kk * 8 + c    ][nt * 8 + g];
                b[1] = ksT[kk * 8 + c + 4][nt * 8 + g];
                mma_tf32(sacc[nt], a, b);
            }
        }
        // store transposed: st[m][l]
#pragma unroll
        for (int nt = 0; nt < 8; nt++) {
            int m = nt * 8 + c * 2;
            st[m    ][lbase + g]     = sacc[nt][0];
            st[m + 1][lbase + g]     = sacc[nt][1];
            st[m    ][lbase + g + 8] = sacc[nt][2];
            st[m + 1][lbase + g + 8] = sacc[nt][3];
        }
    }
    __syncthreads();

    // ---- softmax over m per column l; 2 threads per l (32 m each) ----
    {
        int l     = tid & 63;
        int part  = tid >> 6;
        int mbase = part * 32;
        float mx = -1e30f;
#pragma unroll
        for (int i = 0; i < 32; i++) mx = fmaxf(mx, st[mbase + i][l]);
        smx[part * 64 + l] = mx;
        __syncthreads();
        mx = fmaxf(smx[l], smx[64 + l]);
        float s = 0.f;
        float ev[32];
#pragma unroll
        for (int i = 0; i < 32; i++) {
            float e = __expf(st[mbase + i][l] - mx);
            ev[i] = e;
            s += e;
        }
        ssum[part * 64 + l] = s;
        __syncthreads();
        float inv = 1.f / (ssum[l] + ssum[64 + l]);
#pragma unroll
        for (int i = 0; i < 32; i++)
            st[mbase + i][l] = __uint_as_float(f2tf(ev[i] * inv));
    }
    __syncthreads();

    // ---- O = P V : M=64(l), N=32(d), K=64(m); warp: 16 l x 32 d ----
    float oacc[4][4];
#pragma unroll
    for (int nt = 0; nt < 4; nt++)
#pragma unroll
        for (int r = 0; r < 4; r++) oacc[nt][r] = 0.f;

#pragma unroll
    for (int kk = 0; kk < 8; kk++) {
        uint32_t a[4];
        a[0] = __float_as_uint(st[kk * 8 + c    ][lbase + g]);
        a[1] = __float_as_uint(st[kk * 8 + c    ][lbase + g + 8]);
        a[2] = __float_as_uint(st[kk * 8 + c + 4][lbase + g]);
        a[3] = __float_as_uint(st[kk * 8 + c + 4][lbase + g + 8]);
#pragma unroll
        for (int nt = 0; nt < 4; nt++) {
            uint32_t b[2];
            b[0] = vs[kk * 8 + c    ][nt * 8 + g];
            b[1] = vs[kk * 8 + c + 4][nt * 8 + g];
            mma_tf32(oacc[nt], a, b);
        }
    }
    __syncthreads();   // st reads done; reuse st as O staging [l][d(0..31)]

    {
        int c2 = c * 2;
#pragma unroll
        for (int nt = 0; nt < 4; nt++) {
            int d = nt * 8 + c2;
            st[lbase + g    ][d]     = oacc[nt][0];
            st[lbase + g    ][d + 1] = oacc[nt][1];
            st[lbase + g + 8][d]     = oacc[nt][2];
            st[lbase + g + 8][d + 1] = oacc[nt][3];
        }
    }
    __syncthreads();

    // coalesced O store: 8 lanes per row, 128 B contiguous
#pragma unroll
    for (int s = 0; s < 2; s++) {
        int idx = tid + s * 128;
        int row = idx >> 2;
        int d   = (idx & 3) * 8;
        float4 v0 = make_float4(st[row][d], st[row][d+1], st[row][d+2], st[row][d+3]);
        float4 v1 = make_float4(st[row][d+4], st[row][d+5], st[row][d+6], st[row][d+7]);
        float* p = g_o2 + (size_t)(rowBase + row) * 128 + head * 32 + d;
        reinterpret_cast<float4*>(p)[0] = v0;
        reinterpret_cast<float4*>(p)[1] = v1;
    }
}

// ---------------------------------------------------------------------------
// Blend (analytic scan) + 1x1 conv (smem-staged) + sigmoid gate + residual.
// ---------------------------------------------------------------------------
__global__ void blend_kernel(const float* __restrict__ fcw, const float* __restrict__ fcb,
                             const float* __restrict__ vf, float* __restrict__ out)
{
    __shared__ float enh[32][129];
    __shared__ float fw [32][65];
    __shared__ float fcs[128][76];
    __shared__ float fbs[64];

    int wc = blockIdx.x;     // 0..3
    int h  = blockIdx.y;     // 0..127
    int b  = blockIdx.z;     // 0..3
    int w0 = wc * 32;
    int tid = threadIdx.x;

    for (int idx = tid; idx < 64 * 128; idx += 256) {
        int c = idx >> 7, e = idx & 127;
        fcs[e][c] = fcw[idx];
    }
    if (tid < 64) fbs[tid] = fcb[tid];

    int hiLo = max(0, (h - 4) >> 2);
    int hiHi = min(NH_ - 1, h >> 2);

    for (int s = 0; s < 16; s++) {
        int idx = tid + s * 256;
        int px = idx >> 7;
        int e  = idx & 127;
        int wpix = w0 + px;
        int wiLo = max(0, (wpix - 4) >> 2);
        int wiHi = min(NH_ - 1, wpix >> 2);

        float val = g_nhwc[((size_t)(b * HH + h) * WWID + wpix) * EE + e];
        for (int hi = hiLo; hi <= hiHi; hi++) {
            int lr = (h - hi * 4) * 8;
            for (int wi = wiLo; wi <= wiHi; wi++) {
                int l = lr + (wpix - wi * 4);
                int row = ((hi * NH_ + wi) * 4 + b) * 64 + l;
                val = val * 0.7f + 0.3f * g_att[(size_t)row * 128 + e];
            }
        }
        enh[px][e] = val;
    }
    __syncthreads();

    {
        int px = tid >> 3;
        int cg = tid & 7;
        float acc[8];
#pragma unroll
        for (int j = 0; j < 8; j++) acc[j] = fbs[cg * 8 + j];
#pragma unroll 4
        for (int e = 0; e < 128; e++) {
            float a = enh[px][e];
            const float4* bp = reinterpret_cast<const float4*>(&fcs[e][cg * 8]);
            float4 b0 = bp[0];
            float4 b1 = bp[1];
            acc[0] += a * b0.x; acc[1] += a * b0.y;
            acc[2] += a * b0.z; acc[3] += a * b0.w;
            acc[4] += a * b1.x; acc[5] += a * b1.y;
            acc[6] += a * b1.z; acc[7] += a * b1.w;
        }
#pragma unroll
        for (int j = 0; j < 8; j++)
            fw[px][cg * 8 + j] = 1.f / (1.f + __expf(-acc[j]));
    }
    __syncthreads();

    for (int s = 0; s < 16; s++) {
        int idx = tid + s * 256;
        int px = idx & 31;
        int ch = idx >> 5;
        size_t off = ((size_t)(b * 128 + ch) * HH + h) * WWID + w0 + px;
        out[off] = enh[px][ch] * fw[px][ch & 63] + vf[off];
    }
}

// ---------------------------------------------------------------------------
// Launch
// ---------------------------------------------------------------------------
extern "C" void kernel_launch(void* const* d_in, const int* in_sizes, int n_in,
                              void* d_out, int out_size)
{
    const float* vf    = (const float*)d_in[0];
    const float* mw1   = (const float*)d_in[1];
    const float* mb1   = (const float*)d_in[2];
    const float* mw2   = (const float*)d_in[3];
    const float* mb2   = (const float*)d_in[4];
    const float* aw1   = (const float*)d_in[5];
    const float* ab1   = (const float*)d_in[6];
    const float* aw2   = (const float*)d_in[7];
    const float* ab2   = (const float*)d_in[8];
    const float* ipw   = (const float*)d_in[9];   // [384,128]
    const float* ipb   = (const float*)d_in[10];
    const float* opw   = (const float*)d_in[11];  // [128,128]
    const float* opb   = (const float*)d_in[12];
    const float* fcw   = (const float*)d_in[13];  // [64,128]
    const float* fcb   = (const float*)d_in[14];
    float* out = (float*)d_out;

    void *pqkv, *po2, *patt;
    cudaGetSymbolAddress(&pqkv, g_qkv);
    cudaGetSymbolAddress(&po2,  g_o2);
    cudaGetSymbolAddress(&patt, g_att);

    dim3 cblk(16, 16);
    conv1_kernel<<<dim3(4, 8, 32), cblk>>>(vf, mw1, mb1, aw1, ab1);
    conv2_kernel<<<dim3(4, 8, 64), cblk>>>(mw2, mb2, aw2, ab2);

    // QKV: tokens (gathered from NHWC) x [384,128]^T  -> g_qkv
    gemm_tf32_kernel<true><<<dim3(3, NTOK / 128), 256>>>(
        nullptr, ipw, ipb, (float*)pqkv, 384);

    attn_kernel<<<NWB * 4, 128>>>();

    // out-proj: g_o2 [NTOK,128] x [128,128]^T -> g_att
    gemm_tf32_kernel<false><<<dim3(1, NTOK / 128), 256>>>(
        (const float*)po2, opw, opb, (float*)patt, 128);

    blend_kernel<<<dim3(4, HH, BB), 256>>>(fcw, fcb, vf, out);
}

// round 15
// speedup vs baseline: 1.4648x; 1.2808x over previous
#include <cuda_runtime.h>
#include <math.h>
#include <stdint.h>

// ---------------------------------------------------------------------------
// Problem constants
// ---------------------------------------------------------------------------
#define BB   4      // batch
#define CC   64     // C
#define EE   128    // E = 2C
#define HH   128
#define WWID 128
#define WS_  8
#define STR_ 4
#define NH_  31     // windows per dim
#define NWIN (NH_*NH_)          // 961
#define NWB  (NWIN*BB)          // 3844
#define NTOK (NWB*64)           // 246016 token rows
#define HW   (HH*WWID)          // 16384

// ---------------------------------------------------------------------------
// Scratch (static device globals; no runtime allocation)
// ---------------------------------------------------------------------------
__device__ __align__(16) float    g_mid [BB*64*HW];        // conv1 out (NCHW)
__device__ __align__(16) float    g_nhwc[BB*HW*EE];         // combined0, NHWC
__device__ __align__(16) float    g_qkv [(size_t)NTOK*384];
__device__ __align__(16) float    g_o2  [(size_t)NTOK*128];
__device__ __align__(16) float    g_att [(size_t)NTOK*128];
__device__ __align__(16) uint32_t g_wt  [73728];            // tf32 weights [seg][pos][ic][oc]
__device__ float cbias1[64];    // [br*32 + oc]
__device__ float cbias2[128];   // [br*64 + oc]

// ---------------------------------------------------------------------------
// tf32 helpers
// ---------------------------------------------------------------------------
__device__ __forceinline__ uint32_t f2tf(float f) {
    uint32_t u;
    asm("cvt.rna.tf32.f32 %0, %1;" : "=r"(u) : "f"(f));
    return u;
}

__device__ __forceinline__ void mma_tf32(float* d, const uint32_t* a, const uint32_t* b) {
    asm volatile(
        "mma.sync.aligned.m16n8k8.row.col.f32.tf32.tf32.f32 "
        "{%0,%1,%2,%3}, {%4,%5,%6,%7}, {%8,%9}, {%0,%1,%2,%3};\n"
        : "+f"(d[0]), "+f"(d[1]), "+f"(d[2]), "+f"(d[3])
        : "r"(a[0]), "r"(a[1]), "r"(a[2]), "r"(a[3]), "r"(b[0]), "r"(b[1]));
}

// ---------------------------------------------------------------------------
// Weight pre-transpose: w[oc][ic][3x3] -> g_wt[seg][pos][ic][oc] (tf32 bits)
// seg0: conv1 mag (64ic x 32oc), seg1: conv1 ang,
// seg2: conv2 mag (32ic x 64oc), seg3: conv2 ang.  18432 words each.
// ---------------------------------------------------------------------------
__global__ void wt_transpose_kernel(const float* __restrict__ mw1, const float* __restrict__ aw1,
                                    const float* __restrict__ mw2, const float* __restrict__ aw2)
{
    int flat = blockIdx.x * 256 + threadIdx.x;   // 0..73727
    int seg = flat / 18432;
    int r   = flat - seg * 18432;
    int pos = r / 2048;
    int r2  = r - pos * 2048;
    float v;
    if (seg < 2) {
        int ic = r2 >> 5, oc = r2 & 31;
        const float* w = seg ? aw1 : mw1;        // [32][64][9]
        v = w[oc * 576 + ic * 9 + pos];
    } else {
        int ic = r2 >> 6, oc = r2 & 63;
        const float* w = (seg == 3) ? aw2 : mw2; // [64][32][9]
        v = w[oc * 288 + ic * 9 + pos];
    }
    g_wt[flat] = f2tf(v);
}

__global__ void wt_bias_kernel(const float* __restrict__ mb1, const float* __restrict__ ab1,
                               const float* __restrict__ mb2, const float* __restrict__ ab2)
{
    int t = threadIdx.x;           // 0..191
    if (t < 32)        cbias1[t]      = mb1[t];
    else if (t < 64)   cbias1[t]      = ab1[t - 32];
    else if (t < 128)  cbias2[t - 64] = mb2[t - 64];
    else               cbias2[t - 64] = ab2[t - 128];
}

// ---------------------------------------------------------------------------
// Implicit-GEMM tf32 conv (3x3, SAME).  One block = 8x8 pixel tile (M=64),
// 128 threads (4 warps, 16 px each), N = Cout, K = Cin*9.
// FIRST: vf(NCHW,64ic) -> g_mid(NCHW,32oc) + ReLU
// !FIRST: g_mid(NCHW,32ic) -> g_nhwc(NHWC,64oc within branch half)
// Weights staged from pre-transposed tf32 g_wt (coalesced uint4 copies).
// ---------------------------------------------------------------------------
template<bool FIRST>
__global__ __launch_bounds__(128)
void conv_mma(const float* __restrict__ vin)
{
    constexpr int CIN   = FIRST ? 64 : 32;
    constexpr int COUT  = FIRST ? 32 : 64;
    constexpr int COUTP = FIRST ? 40 : 72;
    constexpr int NF    = COUT / 8;
    constexpr int PLANE = 104;
    constexpr int SHWORDS = FIRST ? (CIN * PLANE) : 4352;

    __shared__ uint32_t shbuf[SHWORDS];
    __shared__ uint32_t Bs[2][CIN * COUTP];

    int tid  = threadIdx.x;
    int lane = tid & 31;
    int warp = tid >> 5;
    int g = lane >> 2, c = lane & 3;

    int x0 = blockIdx.x * 8;
    int y0 = blockIdx.y * 8;
    int z  = blockIdx.z;
    int b  = z >> 1, br = z & 1;

    const uint32_t* wt = g_wt + (FIRST ? 0 : 36864) + br * 18432;

    const float* inB = FIRST ? (vin + (size_t)(b * 128 + br * 64) * HW)
                             : (g_mid + (size_t)(b * 64 + br * 32) * HW);

    // ---- stage halo (10x10 per ic, zero-padded borders) ----
    for (int idx = tid; idx < CIN * 100; idx += 128) {
        int ic = idx / 100;
        int r  = idx - ic * 100;
        int iy = r / 10, ix = r - iy * 10;
        int gy = y0 + iy - 1, gx = x0 + ix - 1;
        float v = 0.f;
        if (gy >= 0 && gy < 128 && gx >= 0 && gx < 128)
            v = inB[(size_t)ic * HW + gy * 128 + gx];
        shbuf[ic * PLANE + iy * 10 + ix] = f2tf(v);
    }

    float acc[NF][4];
#pragma unroll
    for (int nt = 0; nt < NF; nt++)
#pragma unroll
        for (int r = 0; r < 4; r++) acc[nt][r] = 0.f;

#pragma unroll
    for (int pos = 0; pos < 9; pos++) {
        int ky = pos / 3, kx = pos - ky * 3;
        uint32_t* B = Bs[pos & 1];
        // coalesced staging from pre-transposed tf32 weights
        {
            const uint4* src = reinterpret_cast<const uint4*>(wt + pos * CIN * COUT);
#pragma unroll
            for (int i4 = 0; i4 < (CIN * COUT / 4) / 128; i4++) {
                int id = tid + i4 * 128;
                uint4 v = src[id];
                int idx = id * 4;
                int ic = idx / COUT, oc = idx % COUT;
                *reinterpret_cast<uint4*>(&B[ic * COUTP + oc]) = v;
            }
        }
        __syncthreads();

        int abase = (warp * 2 + ky) * 10 + g + kx;
#pragma unroll
        for (int kk = 0; kk < CIN / 8; kk++) {
            int ic0 = kk * 8 + c;
            uint32_t a[4];
            a[0] = shbuf[ic0 * PLANE + abase];
            a[1] = shbuf[ic0 * PLANE + abase + 10];
            a[2] = shbuf[(ic0 + 4) * PLANE + abase];
            a[3] = shbuf[(ic0 + 4) * PLANE + abase + 10];
#pragma unroll
            for (int nt = 0; nt < NF; nt++) {
                uint32_t bb[2];
                bb[0] = B[ic0 * COUTP + nt * 8 + g];
                bb[1] = B[(ic0 + 4) * COUTP + nt * 8 + g];
                mma_tf32(acc[nt], a, bb);
            }
        }
        __syncthreads();
    }

    if (FIRST) {
        // NCHW + bias + ReLU.  lane g -> consecutive x (coalesced per oc).
        int cb = b * 64 + br * 32;
        int rowA = (y0 + warp * 2) * 128 + x0 + g;
        int rowB = rowA + 128;
#pragma unroll
        for (int nt = 0; nt < NF; nt++) {
            int oc0 = nt * 8 + c * 2;
            float b0 = cbias1[br * 32 + oc0];
            float b1 = cbias1[br * 32 + oc0 + 1];
            g_mid[(size_t)(cb + oc0    ) * HW + rowA] = fmaxf(acc[nt][0] + b0, 0.f);
            g_mid[(size_t)(cb + oc0 + 1) * HW + rowA] = fmaxf(acc[nt][1] + b1, 0.f);
            g_mid[(size_t)(cb + oc0    ) * HW + rowB] = fmaxf(acc[nt][2] + b0, 0.f);
            g_mid[(size_t)(cb + oc0 + 1) * HW + rowB] = fmaxf(acc[nt][3] + b1, 0.f);
        }
    } else {
        // smem transpose (reuse shbuf as sout[64][68]) then coalesced NHWC store.
        __syncthreads();
        float* sout = reinterpret_cast<float*>(shbuf);
        int pA = warp * 16 + g;
#pragma unroll
        for (int nt = 0; nt < NF; nt++) {
            int oc0 = nt * 8 + c * 2;
            float b0 = cbias2[br * 64 + oc0];
            float b1 = cbias2[br * 64 + oc0 + 1];
            sout[pA * 68 + oc0]           = acc[nt][0] + b0;
            sout[pA * 68 + oc0 + 1]       = acc[nt][1] + b1;
            sout[(pA + 8) * 68 + oc0]     = acc[nt][2] + b0;
            sout[(pA + 8) * 68 + oc0 + 1] = acc[nt][3] + b1;
        }
        __syncthreads();
        for (int f = tid; f < 1024; f += 128) {
            int p = f >> 4, q = f & 15;
            float4 v = make_float4(sout[p * 68 + q * 4],     sout[p * 68 + q * 4 + 1],
                                   sout[p * 68 + q * 4 + 2], sout[p * 68 + q * 4 + 3]);
            int y = y0 + (p >> 3), x = x0 + (p & 7);
            *reinterpret_cast<float4*>(
                g_nhwc + ((size_t)(b * 128 + y) * 128 + x) * 128 + br * 64 + q * 4) = v;
        }
    }
}

// ---------------------------------------------------------------------------
// tf32 tensor-core GEMM: C[M x N] = A[M x 128] * Wt[N x 128]^T + bias.
// ---------------------------------------------------------------------------
template<bool GATHER>
__global__ __launch_bounds__(256)
void gemm_tf32_kernel(const float* __restrict__ A, const float* __restrict__ Wt,
                      const float* __restrict__ bias, float* __restrict__ C, int N)
{
    __shared__ uint32_t As[32][136];
    __shared__ uint32_t Bs[32][136];

    int tid  = threadIdx.x;
    int lane = tid & 31;
    int wid  = tid >> 5;
    int wm = wid & 1;
    int wn = wid >> 1;
    int m0 = blockIdx.y * 128;
    int n0 = blockIdx.x * 128;

    float acc[4][4][4];
#pragma unroll
    for (int mt = 0; mt < 4; mt++)
#pragma unroll
        for (int nt = 0; nt < 4; nt++)
#pragma unroll
            for (int r = 0; r < 4; r++) acc[mt][nt][r] = 0.f;

    int q = tid & 7;
    const float* arow[4];
    const float* brow[4];
    int rowIdx[4];
#pragma unroll
    for (int s = 0; s < 4; s++) {
        int row = (tid >> 3) + 32 * s;
        rowIdx[s] = row;
        if (GATHER) {
            int m  = m0 + row;
            int l  = m & 63;
            int wb = m >> 6;
            int b  = wb & 3;
            int win = wb >> 2;
            int hi = win / 31;
            int wi = win - hi * 31;
            int h  = hi * 4 + (l >> 3);
            int wc = wi * 4 + (l & 7);
            arow[s] = g_nhwc + ((size_t)((b * 128 + h) * 128 + wc)) * 128;
        } else {
            arow[s] = A + (size_t)(m0 + row) * 128;
        }
        brow[s] = Wt + (size_t)(n0 + row) * 128;
    }

    for (int k0 = 0; k0 < 128; k0 += 32) {
        __syncthreads();
#pragma unroll
        for (int s = 0; s < 4; s++) {
#pragma unroll
            for (int c = 0; c < 4; c++) {
                int k = q + 8 * c;
                As[k][rowIdx[s]] = f2tf(arow[s][k0 + k]);
                Bs[k][rowIdx[s]] = f2tf(brow[s][k0 + k]);
            }
        }
        __syncthreads();

#pragma unroll
        for (int kk = 0; kk < 4; kk++) {
            int c = lane & 3;
            int g = lane >> 2;
            uint32_t a[4][4], b[4][2];
#pragma unroll
            for (int mt = 0; mt < 4; mt++) {
                int r = wm * 64 + mt * 16 + g;
                a[mt][0] = As[kk * 8 + c    ][r];
                a[mt][1] = As[kk * 8 + c    ][r + 8];
                a[mt][2] = As[kk * 8 + c + 4][r];
                a[mt][3] = As[kk * 8 + c + 4][r + 8];
            }
#pragma unroll
            for (int nt = 0; nt < 4; nt++) {
                int n = wn * 32 + nt * 8 + g;
                b[nt][0] = Bs[kk * 8 + c    ][n];
                b[nt][1] = Bs[kk * 8 + c + 4][n];
            }
#pragma unroll
            for (int mt = 0; mt < 4; mt++)
#pragma unroll
                for (int nt = 0; nt < 4; nt++)
                    mma_tf32(acc[mt][nt], a[mt], b[nt]);
        }
    }

    int g  = lane >> 2;
    int c2 = (lane & 3) * 2;
#pragma unroll
    for (int mt = 0; mt < 4; mt++) {
        int row = m0 + wm * 64 + mt * 16 + g;
#pragma unroll
        for (int nt = 0; nt < 4; nt++) {
            int col = n0 + wn * 32 + nt * 8 + c2;
            float b0 = __ldg(bias + col);
            float b1 = __ldg(bias + col + 1);
            float2 v0 = make_float2(acc[mt][nt][0] + b0, acc[mt][nt][1] + b1);
            float2 v1 = make_float2(acc[mt][nt][2] + b0, acc[mt][nt][3] + b1);
            *reinterpret_cast<float2*>(C + (size_t)row * N + col)       = v0;
            *reinterpret_cast<float2*>(C + (size_t)(row + 8) * N + col) = v1;
        }
    }
}

// ---------------------------------------------------------------------------
// Attention core (tensor cores, coalesced I/O) — R13 version (known 150us).
// ---------------------------------------------------------------------------
__global__ __launch_bounds__(128)
void attn_kernel()
{
    __shared__ uint32_t qsT[32][73];
    __shared__ uint32_t ksT[32][73];
    __shared__ uint32_t vs [64][40];
    __shared__ float    st [64][68];
    __shared__ float    smx[128];
    __shared__ float    ssum[128];

    int bx   = blockIdx.x;
    int head = bx & 3;
    int wb   = bx >> 2;
    int rowBase = wb * 64;
    int tid  = threadIdx.x;
    int lane = tid & 31;
    int warp = tid >> 5;
    const float scale = 0.17677669529663687f;  // 1/sqrt(32)

#pragma unroll
    for (int s = 0; s < 4; s++) {
        int idx = tid + s * 128;
        int row = idx >> 3;
        int d   = (idx & 7) * 4;
        const float* p = g_qkv + (size_t)(rowBase + row) * 384 + head * 32 + d;
        float4 qv = *reinterpret_cast<const float4*>(p);
        float4 kv = *reinterpret_cast<const float4*>(p + 128);
        float4 vv = *reinterpret_cast<const float4*>(p + 256);
        qsT[d + 0][row] = f2tf(qv.x * scale);
        qsT[d + 1][row] = f2tf(qv.y * scale);
        qsT[d + 2][row] = f2tf(qv.z * scale);
        qsT[d + 3][row] = f2tf(qv.w * scale);
        ksT[d + 0][row] = f2tf(kv.x);
        ksT[d + 1][row] = f2tf(kv.y);
        ksT[d + 2][row] = f2tf(kv.z);
        ksT[d + 3][row] = f2tf(kv.w);
        uint4 vt;
        vt.x = f2tf(vv.x); vt.y = f2tf(vv.y);
        vt.z = f2tf(vv.z); vt.w = f2tf(vv.w);
        *reinterpret_cast<uint4*>(&vs[row][d]) = vt;
    }
    __syncthreads();

    int g = lane >> 2, c = lane & 3;
    int lbase = warp * 16;

    {
        float sacc[8][4];
#pragma unroll
        for (int nt = 0; nt < 8; nt++)
#pragma unroll
            for (int r = 0; r < 4; r++) sacc[nt][r] = 0.f;

#pragma unroll
        for (int kk = 0; kk < 4; kk++) {
            uint32_t a[4];
            a[0] = qsT[kk * 8 + c    ][lbase + g];
            a[1] = qsT[kk * 8 + c    ][lbase + g + 8];
            a[2] = qsT[kk * 8 + c + 4][lbase + g];
            a[3] = qsT[kk * 8 + c + 4][lbase + g + 8];
#pragma unroll
            for (int nt = 0; nt < 8; nt++) {
                uint32_t b[2];
                b[0] = ksT[kk * 8 + c    ][nt * 8 + g];
                b[1] = ksT[kk * 8 + c + 4][nt * 8 + g];
                mma_tf32(sacc[nt], a, b);
            }
        }
#pragma unroll
        for (int nt = 0; nt < 8; nt++) {
            int m = nt * 8 + c * 2;
            st[m    ][lbase + g]     = sacc[nt][0];
            st[m + 1][lbase + g]     = sacc[nt][1];
            st[m    ][lbase + g + 8] = sacc[nt][2];
            st[m + 1][lbase + g + 8] = sacc[nt][3];
        }
    }
    __syncthreads();

    {
        int l     = tid & 63;
        int part  = tid >> 6;
        int mbase = part * 32;
        float mx = -1e30f;
#pragma unroll
        for (int i = 0; i < 32; i++) mx = fmaxf(mx, st[mbase + i][l]);
        smx[part * 64 + l] = mx;
        __syncthreads();
        mx = fmaxf(smx[l], smx[64 + l]);
        float s = 0.f;
        float ev[32];
#pragma unroll
        for (int i = 0; i < 32; i++) {
            float e = __expf(st[mbase + i][l] - mx);
            ev[i] = e;
            s += e;
        }
        ssum[part * 64 + l] = s;
        __syncthreads();
        float inv = 1.f / (ssum[l] + ssum[64 + l]);
#pragma unroll
        for (int i = 0; i < 32; i++)
            st[mbase + i][l] = __uint_as_float(f2tf(ev[i] * inv));
    }
    __syncthreads();

    float oacc[4][4];
#pragma unroll
    for (int nt = 0; nt < 4; nt++)
#pragma unroll
        for (int r = 0; r < 4; r++) oacc[nt][r] = 0.f;

#pragma unroll
    for (int kk = 0; kk < 8; kk++) {
        uint32_t a[4];
        a[0] = __float_as_uint(st[kk * 8 + c    ][lbase + g]);
        a[1] = __float_as_uint(st[kk * 8 + c    ][lbase + g + 8]);
        a[2] = __float_as_uint(st[kk * 8 + c + 4][lbase + g]);
        a[3] = __float_as_uint(st[kk * 8 + c + 4][lbase + g + 8]);
#pragma unroll
        for (int nt = 0; nt < 4; nt++) {
            uint32_t b[2];
            b[0] = vs[kk * 8 + c    ][nt * 8 + g];
            b[1] = vs[kk * 8 + c + 4][nt * 8 + g];
            mma_tf32(oacc[nt], a, b);
        }
    }
    __syncthreads();

    {
        int c2 = c * 2;
#pragma unroll
        for (int nt = 0; nt < 4; nt++) {
            int d = nt * 8 + c2;
            st[lbase + g    ][d]     = oacc[nt][0];
            st[lbase + g    ][d + 1] = oacc[nt][1];
            st[lbase + g + 8][d]     = oacc[nt][2];
            st[lbase + g + 8][d + 1] = oacc[nt][3];
        }
    }
    __syncthreads();

#pragma unroll
    for (int s = 0; s < 2; s++) {
        int idx = tid + s * 128;
        int row = idx >> 2;
        int d   = (idx & 3) * 8;
        float4 v0 = make_float4(st[row][d], st[row][d+1], st[row][d+2], st[row][d+3]);
        float4 v1 = make_float4(st[row][d+4], st[row][d+5], st[row][d+6], st[row][d+7]);
        float* p = g_o2 + (size_t)(rowBase + row) * 128 + head * 32 + d;
        reinterpret_cast<float4*>(p)[0] = v0;
        reinterpret_cast<float4*>(p)[1] = v1;
    }
}

// ---------------------------------------------------------------------------
// Blend (analytic scan) + 1x1 conv (smem-staged) + sigmoid gate + residual.
// ---------------------------------------------------------------------------
__global__ void blend_kernel(const float* __restrict__ fcw, const float* __restrict__ fcb,
                             const float* __restrict__ vf, float* __restrict__ out)
{
    __shared__ float enh[32][129];
    __shared__ float fw [32][65];
    __shared__ float fcs[128][76];
    __shared__ float fbs[64];

    int wc = blockIdx.x;     // 0..3
    int h  = blockIdx.y;     // 0..127
    int b  = blockIdx.z;     // 0..3
    int w0 = wc * 32;
    int tid = threadIdx.x;

    for (int idx = tid; idx < 64 * 128; idx += 256) {
        int c = idx >> 7, e = idx & 127;
        fcs[e][c] = fcw[idx];
    }
    if (tid < 64) fbs[tid] = fcb[tid];

    int hiLo = max(0, (h - 4) >> 2);
    int hiHi = min(NH_ - 1, h >> 2);

    for (int s = 0; s < 16; s++) {
        int idx = tid + s * 256;
        int px = idx >> 7;
        int e  = idx & 127;
        int wpix = w0 + px;
        int wiLo = max(0, (wpix - 4) >> 2);
        int wiHi = min(NH_ - 1, wpix >> 2);

        float val = g_nhwc[((size_t)(b * HH + h) * WWID + wpix) * EE + e];
        for (int hi = hiLo; hi <= hiHi; hi++) {
            int lr = (h - hi * 4) * 8;
            for (int wi = wiLo; wi <= wiHi; wi++) {
                int l = lr + (wpix - wi * 4);
                int row = ((hi * NH_ + wi) * 4 + b) * 64 + l;
                val = val * 0.7f + 0.3f * g_att[(size_t)row * 128 + e];
            }
        }
        enh[px][e] = val;
    }
    __syncthreads();

    {
        int px = tid >> 3;
        int cg = tid & 7;
        float acc[8];
#pragma unroll
        for (int j = 0; j < 8; j++) acc[j] = fbs[cg * 8 + j];
#pragma unroll 4
        for (int e = 0; e < 128; e++) {
            float a = enh[px][e];
            const float4* bp = reinterpret_cast<const float4*>(&fcs[e][cg * 8]);
            float4 b0 = bp[0];
            float4 b1 = bp[1];
            acc[0] += a * b0.x; acc[1] += a * b0.y;
            acc[2] += a * b0.z; acc[3] += a * b0.w;
            acc[4] += a * b1.x; acc[5] += a * b1.y;
            acc[6] += a * b1.z; acc[7] += a * b1.w;
        }
#pragma unroll
        for (int j = 0; j < 8; j++)
            fw[px][cg * 8 + j] = 1.f / (1.f + __expf(-acc[j]));
    }
    __syncthreads();

    for (int s = 0; s < 16; s++) {
        int idx = tid + s * 256;
        int px = idx & 31;
        int ch = idx >> 5;
        size_t off = ((size_t)(b * 128 + ch) * HH + h) * WWID + w0 + px;
        out[off] = enh[px][ch] * fw[px][ch & 63] + vf[off];
    }
}

// ---------------------------------------------------------------------------
// Launch
// ---------------------------------------------------------------------------
extern "C" void kernel_launch(void* const* d_in, const int* in_sizes, int n_in,
                              void* d_out, int out_size)
{
    const float* vf    = (const float*)d_in[0];
    const float* mw1   = (const float*)d_in[1];
    const float* mb1   = (const float*)d_in[2];
    const float* mw2   = (const float*)d_in[3];
    const float* mb2   = (const float*)d_in[4];
    const float* aw1   = (const float*)d_in[5];
    const float* ab1   = (const float*)d_in[6];
    const float* aw2   = (const float*)d_in[7];
    const float* ab2   = (const float*)d_in[8];
    const float* ipw   = (const float*)d_in[9];   // [384,128]
    const float* ipb   = (const float*)d_in[10];
    const float* opw   = (const float*)d_in[11];  // [128,128]
    const float* opb   = (const float*)d_in[12];
    const float* fcw   = (const float*)d_in[13];  // [64,128]
    const float* fcb   = (const float*)d_in[14];
    float* out = (float*)d_out;

    void *pqkv, *po2, *patt;
    cudaGetSymbolAddress(&pqkv, g_qkv);
    cudaGetSymbolAddress(&po2,  g_o2);
    cudaGetSymbolAddress(&patt, g_att);

    // weight/bias pre-transpose (tiny)
    wt_transpose_kernel<<<288, 256>>>(mw1, aw1, mw2, aw2);
    wt_bias_kernel<<<1, 192>>>(mb1, ab1, mb2, ab2);

    // convs: implicit-GEMM tf32 with pre-transposed weights
    conv_mma<true ><<<dim3(16, 16, 8), 128>>>(vf);
    conv_mma<false><<<dim3(16, 16, 8), 128>>>(nullptr);

    // QKV: tokens (gathered from NHWC) x [384,128]^T  -> g_qkv
    gemm_tf32_kernel<true><<<dim3(3, NTOK / 128), 256>>>(
        nullptr, ipw, ipb, (float*)pqkv, 384);

    attn_kernel<<<NWB * 4, 128>>>();

    // out-proj: g_o2 [NTOK,128] x [128,128]^T -> g_att
    gemm_tf32_kernel<false><<<dim3(1, NTOK / 128), 256>>>(
        (const float*)po2, opw, opb, (float*)patt, 128);

    blend_kernel<<<dim3(4, HH, BB), 256>>>(fcw, fcb, vf, out);
}

// round 16
// speedup vs baseline: 1.9003x; 1.2973x over previous
#include <cuda_runtime.h>
#include <math.h>
#include <stdint.h>

// ---------------------------------------------------------------------------
// Problem constants
// ---------------------------------------------------------------------------
#define BB   4      // batch
#define CC   64     // C
#define EE   128    // E = 2C
#define HH   128
#define WWID 128
#define WS_  8
#define STR_ 4
#define NH_  31     // windows per dim
#define NWIN (NH_*NH_)          // 961
#define NWB  (NWIN*BB)          // 3844
#define NTOK (NWB*64)           // 246016 token rows
#define HW   (HH*WWID)          // 16384
#define NPIX (BB*HW)            // 65536 pixel rows

// ---------------------------------------------------------------------------
// Scratch (static device globals; no runtime allocation)
// ---------------------------------------------------------------------------
__device__ __align__(16) float    g_mid [BB*64*HW];        // conv1 out (NCHW)
__device__ __align__(16) float    g_nhwc[BB*HW*EE];         // combined0, NHWC
__device__ __align__(16) float    g_qkv [(size_t)NPIX*384]; // per-PIXEL qkv
__device__ __align__(16) float    g_o2  [(size_t)NTOK*128];
__device__ __align__(16) float    g_att [(size_t)NTOK*128];
__device__ __align__(16) uint32_t g_wt  [73728];            // tf32 weights [seg][pos][ic][oc]
__device__ float cbias1[64];    // [br*32 + oc]
__device__ float cbias2[128];   // [br*64 + oc]

// ---------------------------------------------------------------------------
// tf32 helpers
// ---------------------------------------------------------------------------
__device__ __forceinline__ uint32_t f2tf(float f) {
    uint32_t u;
    asm("cvt.rna.tf32.f32 %0, %1;" : "=r"(u) : "f"(f));
    return u;
}

__device__ __forceinline__ void mma_tf32(float* d, const uint32_t* a, const uint32_t* b) {
    asm volatile(
        "mma.sync.aligned.m16n8k8.row.col.f32.tf32.tf32.f32 "
        "{%0,%1,%2,%3}, {%4,%5,%6,%7}, {%8,%9}, {%0,%1,%2,%3};\n"
        : "+f"(d[0]), "+f"(d[1]), "+f"(d[2]), "+f"(d[3])
        : "r"(a[0]), "r"(a[1]), "r"(a[2]), "r"(a[3]), "r"(b[0]), "r"(b[1]));
}

// ---------------------------------------------------------------------------
// Weight pre-transpose: w[oc][ic][3x3] -> g_wt[seg][pos][ic][oc] (tf32 bits)
// ---------------------------------------------------------------------------
__global__ void wt_transpose_kernel(const float* __restrict__ mw1, const float* __restrict__ aw1,
                                    const float* __restrict__ mw2, const float* __restrict__ aw2)
{
    int flat = blockIdx.x * 256 + threadIdx.x;   // 0..73727
    int seg = flat / 18432;
    int r   = flat - seg * 18432;
    int pos = r / 2048;
    int r2  = r - pos * 2048;
    float v;
    if (seg < 2) {
        int ic = r2 >> 5, oc = r2 & 31;
        const float* w = seg ? aw1 : mw1;        // [32][64][9]
        v = w[oc * 576 + ic * 9 + pos];
    } else {
        int ic = r2 >> 6, oc = r2 & 63;
        const float* w = (seg == 3) ? aw2 : mw2; // [64][32][9]
        v = w[oc * 288 + ic * 9 + pos];
    }
    g_wt[flat] = f2tf(v);
}

__global__ void wt_bias_kernel(const float* __restrict__ mb1, const float* __restrict__ ab1,
                               const float* __restrict__ mb2, const float* __restrict__ ab2)
{
    int t = threadIdx.x;           // 0..191
    if (t < 32)        cbias1[t]      = mb1[t];
    else if (t < 64)   cbias1[t]      = ab1[t - 32];
    else if (t < 128)  cbias2[t - 64] = mb2[t - 64];
    else               cbias2[t - 64] = ab2[t - 128];
}

// ---------------------------------------------------------------------------
// Implicit-GEMM tf32 conv (3x3, SAME).  8x8 px tile, 128 thr, N=Cout, K=Cin*9.
// ---------------------------------------------------------------------------
template<bool FIRST>
__global__ __launch_bounds__(128)
void conv_mma(const float* __restrict__ vin)
{
    constexpr int CIN   = FIRST ? 64 : 32;
    constexpr int COUT  = FIRST ? 32 : 64;
    constexpr int COUTP = FIRST ? 40 : 72;
    constexpr int NF    = COUT / 8;
    constexpr int PLANE = 104;
    constexpr int SHWORDS = FIRST ? (CIN * PLANE) : 4352;

    __shared__ uint32_t shbuf[SHWORDS];
    __shared__ uint32_t Bs[2][CIN * COUTP];

    int tid  = threadIdx.x;
    int lane = tid & 31;
    int warp = tid >> 5;
    int g = lane >> 2, c = lane & 3;

    int x0 = blockIdx.x * 8;
    int y0 = blockIdx.y * 8;
    int z  = blockIdx.z;
    int b  = z >> 1, br = z & 1;

    const uint32_t* wt = g_wt + (FIRST ? 0 : 36864) + br * 18432;

    const float* inB = FIRST ? (vin + (size_t)(b * 128 + br * 64) * HW)
                             : (g_mid + (size_t)(b * 64 + br * 32) * HW);

    for (int idx = tid; idx < CIN * 100; idx += 128) {
        int ic = idx / 100;
        int r  = idx - ic * 100;
        int iy = r / 10, ix = r - iy * 10;
        int gy = y0 + iy - 1, gx = x0 + ix - 1;
        float v = 0.f;
        if (gy >= 0 && gy < 128 && gx >= 0 && gx < 128)
            v = inB[(size_t)ic * HW + gy * 128 + gx];
        shbuf[ic * PLANE + iy * 10 + ix] = f2tf(v);
    }

    float acc[NF][4];
#pragma unroll
    for (int nt = 0; nt < NF; nt++)
#pragma unroll
        for (int r = 0; r < 4; r++) acc[nt][r] = 0.f;

#pragma unroll
    for (int pos = 0; pos < 9; pos++) {
        int ky = pos / 3, kx = pos - ky * 3;
        uint32_t* B = Bs[pos & 1];
        {
            const uint4* src = reinterpret_cast<const uint4*>(wt + pos * CIN * COUT);
#pragma unroll
            for (int i4 = 0; i4 < (CIN * COUT / 4) / 128; i4++) {
                int id = tid + i4 * 128;
                uint4 v = src[id];
                int idx = id * 4;
                int ic = idx / COUT, oc = idx % COUT;
                *reinterpret_cast<uint4*>(&B[ic * COUTP + oc]) = v;
            }
        }
        __syncthreads();

        int abase = (warp * 2 + ky) * 10 + g + kx;
#pragma unroll
        for (int kk = 0; kk < CIN / 8; kk++) {
            int ic0 = kk * 8 + c;
            uint32_t a[4];
            a[0] = shbuf[ic0 * PLANE + abase];
            a[1] = shbuf[ic0 * PLANE + abase + 10];
            a[2] = shbuf[(ic0 + 4) * PLANE + abase];
            a[3] = shbuf[(ic0 + 4) * PLANE + abase + 10];
#pragma unroll
            for (int nt = 0; nt < NF; nt++) {
                uint32_t bb[2];
                bb[0] = B[ic0 * COUTP + nt * 8 + g];
                bb[1] = B[(ic0 + 4) * COUTP + nt * 8 + g];
                mma_tf32(acc[nt], a, bb);
            }
        }
        __syncthreads();
    }

    if (FIRST) {
        int cb = b * 64 + br * 32;
        int rowA = (y0 + warp * 2) * 128 + x0 + g;
        int rowB = rowA + 128;
#pragma unroll
        for (int nt = 0; nt < NF; nt++) {
            int oc0 = nt * 8 + c * 2;
            float b0 = cbias1[br * 32 + oc0];
            float b1 = cbias1[br * 32 + oc0 + 1];
            g_mid[(size_t)(cb + oc0    ) * HW + rowA] = fmaxf(acc[nt][0] + b0, 0.f);
            g_mid[(size_t)(cb + oc0 + 1) * HW + rowA] = fmaxf(acc[nt][1] + b1, 0.f);
            g_mid[(size_t)(cb + oc0    ) * HW + rowB] = fmaxf(acc[nt][2] + b0, 0.f);
            g_mid[(size_t)(cb + oc0 + 1) * HW + rowB] = fmaxf(acc[nt][3] + b1, 0.f);
        }
    } else {
        __syncthreads();
        float* sout = reinterpret_cast<float*>(shbuf);
        int pA = warp * 16 + g;
#pragma unroll
        for (int nt = 0; nt < NF; nt++) {
            int oc0 = nt * 8 + c * 2;
            float b0 = cbias2[br * 64 + oc0];
            float b1 = cbias2[br * 64 + oc0 + 1];
            sout[pA * 68 + oc0]           = acc[nt][0] + b0;
            sout[pA * 68 + oc0 + 1]       = acc[nt][1] + b1;
            sout[(pA + 8) * 68 + oc0]     = acc[nt][2] + b0;
            sout[(pA + 8) * 68 + oc0 + 1] = acc[nt][3] + b1;
        }
        __syncthreads();
        for (int f = tid; f < 1024; f += 128) {
            int p = f >> 4, q = f & 15;
            float4 v = make_float4(sout[p * 68 + q * 4],     sout[p * 68 + q * 4 + 1],
                                   sout[p * 68 + q * 4 + 2], sout[p * 68 + q * 4 + 3]);
            int y = y0 + (p >> 3), x = x0 + (p & 7);
            *reinterpret_cast<float4*>(
                g_nhwc + ((size_t)(b * 128 + y) * 128 + x) * 128 + br * 64 + q * 4) = v;
        }
    }
}

// ---------------------------------------------------------------------------
// tf32 tensor-core GEMM: C[M x N] = A[M x 128] * Wt[N x 128]^T + bias.
// ---------------------------------------------------------------------------
__global__ __launch_bounds__(256)
void gemm_tf32_kernel(const float* __restrict__ A, const float* __restrict__ Wt,
                      const float* __restrict__ bias, float* __restrict__ C, int N)
{
    __shared__ uint32_t As[32][136];
    __shared__ uint32_t Bs[32][136];

    int tid  = threadIdx.x;
    int lane = tid & 31;
    int wid  = tid >> 5;
    int wm = wid & 1;
    int wn = wid >> 1;
    int m0 = blockIdx.y * 128;
    int n0 = blockIdx.x * 128;

    float acc[4][4][4];
#pragma unroll
    for (int mt = 0; mt < 4; mt++)
#pragma unroll
        for (int nt = 0; nt < 4; nt++)
#pragma unroll
            for (int r = 0; r < 4; r++) acc[mt][nt][r] = 0.f;

    int q = tid & 7;
    const float* arow[4];
    const float* brow[4];
    int rowIdx[4];
#pragma unroll
    for (int s = 0; s < 4; s++) {
        int row = (tid >> 3) + 32 * s;
        rowIdx[s] = row;
        arow[s] = A + (size_t)(m0 + row) * 128;
        brow[s] = Wt + (size_t)(n0 + row) * 128;
    }

    for (int k0 = 0; k0 < 128; k0 += 32) {
        __syncthreads();
#pragma unroll
        for (int s = 0; s < 4; s++) {
#pragma unroll
            for (int c = 0; c < 4; c++) {
                int k = q + 8 * c;
                As[k][rowIdx[s]] = f2tf(arow[s][k0 + k]);
                Bs[k][rowIdx[s]] = f2tf(brow[s][k0 + k]);
            }
        }
        __syncthreads();

#pragma unroll
        for (int kk = 0; kk < 4; kk++) {
            int c = lane & 3;
            int g = lane >> 2;
            uint32_t a[4][4], b[4][2];
#pragma unroll
            for (int mt = 0; mt < 4; mt++) {
                int r = wm * 64 + mt * 16 + g;
                a[mt][0] = As[kk * 8 + c    ][r];
                a[mt][1] = As[kk * 8 + c    ][r + 8];
                a[mt][2] = As[kk * 8 + c + 4][r];
                a[mt][3] = As[kk * 8 + c + 4][r + 8];
            }
#pragma unroll
            for (int nt = 0; nt < 4; nt++) {
                int n = wn * 32 + nt * 8 + g;
                b[nt][0] = Bs[kk * 8 + c    ][n];
                b[nt][1] = Bs[kk * 8 + c + 4][n];
            }
#pragma unroll
            for (int mt = 0; mt < 4; mt++)
#pragma unroll
                for (int nt = 0; nt < 4; nt++)
                    mma_tf32(acc[mt][nt], a[mt], b[nt]);
        }
    }

    int g  = lane >> 2;
    int c2 = (lane & 3) * 2;
#pragma unroll
    for (int mt = 0; mt < 4; mt++) {
        int row = m0 + wm * 64 + mt * 16 + g;
#pragma unroll
        for (int nt = 0; nt < 4; nt++) {
            int col = n0 + wn * 32 + nt * 8 + c2;
            float b0 = __ldg(bias + col);
            float b1 = __ldg(bias + col + 1);
            float2 v0 = make_float2(acc[mt][nt][0] + b0, acc[mt][nt][1] + b1);
            float2 v1 = make_float2(acc[mt][nt][2] + b0, acc[mt][nt][3] + b1);
            *reinterpret_cast<float2*>(C + (size_t)row * N + col)       = v0;
            *reinterpret_cast<float2*>(C + (size_t)(row + 8) * N + col) = v1;
        }
    }
}

// ---------------------------------------------------------------------------
// Attention core (tensor cores, coalesced I/O).  Q/K/V gathered from the
// per-PIXEL qkv buffer (windows share pixels -> 4x less QKV GEMM work and
// L2-amplified reads here).  One block (128 thr) per (window*batch, head).
// ---------------------------------------------------------------------------
__global__ __launch_bounds__(128)
void attn_kernel()
{
    __shared__ uint32_t qsT[32][73];
    __shared__ uint32_t ksT[32][73];
    __shared__ uint32_t vs [64][40];
    __shared__ float    st [64][68];
    __shared__ float    smx[128];
    __shared__ float    ssum[128];

    int bx   = blockIdx.x;
    int head = bx & 3;
    int wb   = bx >> 2;
    int rowBase = wb * 64;          // token rows for O output
    int b   = wb & 3;
    int win = wb >> 2;
    int hi  = win / NH_;
    int wi  = win - hi * NH_;
    int tid  = threadIdx.x;
    int lane = tid & 31;
    int warp = tid >> 5;
    const float scale = 0.17677669529663687f;  // 1/sqrt(32)

    // ---- coalesced gather of Q,K,V from per-pixel qkv ----
#pragma unroll
    for (int s = 0; s < 4; s++) {
        int idx = tid + s * 128;
        int l   = idx >> 3;                  // token 0..63
        int d   = (idx & 7) * 4;
        int h   = hi * 4 + (l >> 3);
        int w   = wi * 4 + (l & 7);
        const float* p = g_qkv + ((size_t)((b * 128 + h) * 128 + w)) * 384 + head * 32 + d;
        float4 qv = *reinterpret_cast<const float4*>(p);
        float4 kv = *reinterpret_cast<const float4*>(p + 128);
        float4 vv = *reinterpret_cast<const float4*>(p + 256);
        qsT[d + 0][l] = f2tf(qv.x * scale);
        qsT[d + 1][l] = f2tf(qv.y * scale);
        qsT[d + 2][l] = f2tf(qv.z * scale);
        qsT[d + 3][l] = f2tf(qv.w * scale);
        ksT[d + 0][l] = f2tf(kv.x);
        ksT[d + 1][l] = f2tf(kv.y);
        ksT[d + 2][l] = f2tf(kv.z);
        ksT[d + 3][l] = f2tf(kv.w);
        uint4 vt;
        vt.x = f2tf(vv.x); vt.y = f2tf(vv.y);
        vt.z = f2tf(vv.z); vt.w = f2tf(vv.w);
        *reinterpret_cast<uint4*>(&vs[l][d]) = vt;
    }
    __syncthreads();

    int g = lane >> 2, c = lane & 3;
    int lbase = warp * 16;

    {
        float sacc[8][4];
#pragma unroll
        for (int nt = 0; nt < 8; nt++)
#pragma unroll
            for (int r = 0; r < 4; r++) sacc[nt][r] = 0.f;

#pragma unroll
        for (int kk = 0; kk < 4; kk++) {
            uint32_t a[4];
            a[0] = qsT[kk * 8 + c    ][lbase + g];
            a[1] = qsT[kk * 8 + c    ][lbase + g + 8];
            a[2] = qsT[kk * 8 + c + 4][lbase + g];
            a[3] = qsT[kk * 8 + c + 4][lbase + g + 8];
#pragma unroll
            for (int nt = 0; nt < 8; nt++) {
                uint32_t b2[2];
                b2[0] = ksT[kk * 8 + c    ][nt * 8 + g];
                b2[1] = ksT[kk * 8 + c + 4][nt * 8 + g];
                mma_tf32(sacc[nt], a, b2);
            }
        }
#pragma unroll
        for (int nt = 0; nt < 8; nt++) {
            int m = nt * 8 + c * 2;
            st[m    ][lbase + g]     = sacc[nt][0];
            st[m + 1][lbase + g]     = sacc[nt][1];
            st[m    ][lbase + g + 8] = sacc[nt][2];
            st[m + 1][lbase + g + 8] = sacc[nt][3];
        }
    }
    __syncthreads();

    {
        int l     = tid & 63;
        int part  = tid >> 6;
        int mbase = part * 32;
        float mx = -1e30f;
#pragma unroll
        for (int i = 0; i < 32; i++) mx = fmaxf(mx, st[mbase + i][l]);
        smx[part * 64 + l] = mx;
        __syncthreads();
        mx = fmaxf(smx[l], smx[64 + l]);
        float s = 0.f;
        float ev[32];
#pragma unroll
        for (int i = 0; i < 32; i++) {
            float e = __expf(st[mbase + i][l] - mx);
            ev[i] = e;
            s += e;
        }
        ssum[part * 64 + l] = s;
        __syncthreads();
        float inv = 1.f / (ssum[l] + ssum[64 + l]);
#pragma unroll
        for (int i = 0; i < 32; i++)
            st[mbase + i][l] = __uint_as_float(f2tf(ev[i] * inv));
    }
    __syncthreads();

    float oacc[4][4];
#pragma unroll
    for (int nt = 0; nt < 4; nt++)
#pragma unroll
        for (int r = 0; r < 4; r++) oacc[nt][r] = 0.f;

#pragma unroll
    for (int kk = 0; kk < 8; kk++) {
        uint32_t a[4];
        a[0] = __float_as_uint(st[kk * 8 + c    ][lbase + g]);
        a[1] = __float_as_uint(st[kk * 8 + c    ][lbase + g + 8]);
        a[2] = __float_as_uint(st[kk * 8 + c + 4][lbase + g]);
        a[3] = __float_as_uint(st[kk * 8 + c + 4][lbase + g + 8]);
#pragma unroll
        for (int nt = 0; nt < 4; nt++) {
            uint32_t b2[2];
            b2[0] = vs[kk * 8 + c    ][nt * 8 + g];
            b2[1] = vs[kk * 8 + c + 4][nt * 8 + g];
            mma_tf32(oacc[nt], a, b2);
        }
    }
    __syncthreads();

    {
        int c2 = c * 2;
#pragma unroll
        for (int nt = 0; nt < 4; nt++) {
            int d = nt * 8 + c2;
            st[lbase + g    ][d]     = oacc[nt][0];
            st[lbase + g    ][d + 1] = oacc[nt][1];
            st[lbase + g + 8][d]     = oacc[nt][2];
            st[lbase + g + 8][d + 1] = oacc[nt][3];
        }
    }
    __syncthreads();

#pragma unroll
    for (int s = 0; s < 2; s++) {
        int idx = tid + s * 128;
        int row = idx >> 2;
        int d   = (idx & 3) * 8;
        float4 v0 = make_float4(st[row][d], st[row][d+1], st[row][d+2], st[row][d+3]);
        float4 v1 = make_float4(st[row][d+4], st[row][d+5], st[row][d+6], st[row][d+7]);
        float* p = g_o2 + (size_t)(rowBase + row) * 128 + head * 32 + d;
        reinterpret_cast<float4*>(p)[0] = v0;
        reinterpret_cast<float4*>(p)[1] = v1;
    }
}

// ---------------------------------------------------------------------------
// Blend (analytic scan) + 1x1 conv (smem-staged) + sigmoid gate + residual.
// ---------------------------------------------------------------------------
__global__ void blend_kernel(const float* __restrict__ fcw, const float* __restrict__ fcb,
                             const float* __restrict__ vf, float* __restrict__ out)
{
    __shared__ float enh[32][129];
    __shared__ float fw [32][65];
    __shared__ float fcs[128][76];
    __shared__ float fbs[64];

    int wc = blockIdx.x;     // 0..3
    int h  = blockIdx.y;     // 0..127
    int b  = blockIdx.z;     // 0..3
    int w0 = wc * 32;
    int tid = threadIdx.x;

    for (int idx = tid; idx < 64 * 128; idx += 256) {
        int c = idx >> 7, e = idx & 127;
        fcs[e][c] = fcw[idx];
    }
    if (tid < 64) fbs[tid] = fcb[tid];

    int hiLo = max(0, (h - 4) >> 2);
    int hiHi = min(NH_ - 1, h >> 2);

    for (int s = 0; s < 16; s++) {
        int idx = tid + s * 256;
        int px = idx >> 7;
        int e  = idx & 127;
        int wpix = w0 + px;
        int wiLo = max(0, (wpix - 4) >> 2);
        int wiHi = min(NH_ - 1, wpix >> 2);

        float val = g_nhwc[((size_t)(b * HH + h) * WWID + wpix) * EE + e];
        for (int hi = hiLo; hi <= hiHi; hi++) {
            int lr = (h - hi * 4) * 8;
            for (int wi = wiLo; wi <= wiHi; wi++) {
                int l = lr + (wpix - wi * 4);
                int row = ((hi * NH_ + wi) * 4 + b) * 64 + l;
                val = val * 0.7f + 0.3f * g_att[(size_t)row * 128 + e];
            }
        }
        enh[px][e] = val;
    }
    __syncthreads();

    {
        int px = tid >> 3;
        int cg = tid & 7;
        float acc[8];
#pragma unroll
        for (int j = 0; j < 8; j++) acc[j] = fbs[cg * 8 + j];
#pragma unroll 4
        for (int e = 0; e < 128; e++) {
            float a = enh[px][e];
            const float4* bp = reinterpret_cast<const float4*>(&fcs[e][cg * 8]);
            float4 b0 = bp[0];
            float4 b1 = bp[1];
            acc[0] += a * b0.x; acc[1] += a * b0.y;
            acc[2] += a * b0.z; acc[3] += a * b0.w;
            acc[4] += a * b1.x; acc[5] += a * b1.y;
            acc[6] += a * b1.z; acc[7] += a * b1.w;
        }
#pragma unroll
        for (int j = 0; j < 8; j++)
            fw[px][cg * 8 + j] = 1.f / (1.f + __expf(-acc[j]));
    }
    __syncthreads();

    for (int s = 0; s < 16; s++) {
        int idx = tid + s * 256;
        int px = idx & 31;
        int ch = idx >> 5;
        size_t off = ((size_t)(b * 128 + ch) * HH + h) * WWID + w0 + px;
        out[off] = enh[px][ch] * fw[px][ch & 63] + vf[off];
    }
}

// ---------------------------------------------------------------------------
// Launch
// ---------------------------------------------------------------------------
extern "C" void kernel_launch(void* const* d_in, const int* in_sizes, int n_in,
                              void* d_out, int out_size)
{
    const float* vf    = (const float*)d_in[0];
    const float* mw1   = (const float*)d_in[1];
    const float* mb1   = (const float*)d_in[2];
    const float* mw2   = (const float*)d_in[3];
    const float* mb2   = (const float*)d_in[4];
    const float* aw1   = (const float*)d_in[5];
    const float* ab1   = (const float*)d_in[6];
    const float* aw2   = (const float*)d_in[7];
    const float* ab2   = (const float*)d_in[8];
    const float* ipw   = (const float*)d_in[9];   // [384,128]
    const float* ipb   = (const float*)d_in[10];
    const float* opw   = (const float*)d_in[11];  // [128,128]
    const float* opb   = (const float*)d_in[12];
    const float* fcw   = (const float*)d_in[13];  // [64,128]
    const float* fcb   = (const float*)d_in[14];
    float* out = (float*)d_out;

    void *pnhwc, *pqkv, *po2, *patt;
    cudaGetSymbolAddress(&pnhwc, g_nhwc);
    cudaGetSymbolAddress(&pqkv, g_qkv);
    cudaGetSymbolAddress(&po2,  g_o2);
    cudaGetSymbolAddress(&patt, g_att);

    // weight/bias pre-transpose (tiny)
    wt_transpose_kernel<<<288, 256>>>(mw1, aw1, mw2, aw2);
    wt_bias_kernel<<<1, 192>>>(mb1, ab1, mb2, ab2);

    // convs: implicit-GEMM tf32 with pre-transposed weights
    conv_mma<true ><<<dim3(16, 16, 8), 128>>>(vf);
    conv_mma<false><<<dim3(16, 16, 8), 128>>>(nullptr);

    // QKV per PIXEL (not per token): g_nhwc [65536,128] x [384,128]^T -> g_qkv
    gemm_tf32_kernel<<<dim3(3, NPIX / 128), 256>>>(
        (const float*)pnhwc, ipw, ipb, (float*)pqkv, 384);

    attn_kernel<<<NWB * 4, 128>>>();

    // out-proj: g_o2 [NTOK,128] x [128,128]^T -> g_att
    gemm_tf32_kernel<<<dim3(1, NTOK / 128), 256>>>(
        (const float*)po2, opw, opb, (float*)patt, 128);

    blend_kernel<<<dim3(4, HH, BB), 256>>>(fcw, fcb, vf, out);
}

// round 17
// speedup vs baseline: 2.0057x; 1.0554x over previous
#include <cuda_runtime.h>
#include <math.h>
#include <stdint.h>

// ---------------------------------------------------------------------------
// Problem constants
// ---------------------------------------------------------------------------
#define BB   4      // batch
#define CC   64     // C
#define EE   128    // E = 2C
#define HH   128
#define WWID 128
#define WS_  8
#define STR_ 4
#define NH_  31     // windows per dim
#define NWIN (NH_*NH_)          // 961
#define NWB  (NWIN*BB)          // 3844
#define NTOK (NWB*64)           // 246016 token rows
#define HW   (HH*WWID)          // 16384
#define NPIX (BB*HW)            // 65536 pixel rows

// ---------------------------------------------------------------------------
// Scratch (static device globals; no runtime allocation)
// ---------------------------------------------------------------------------
__device__ __align__(16) float    g_mid [BB*64*HW];        // conv1 out (NCHW)
__device__ __align__(16) float    g_nhwc[BB*HW*EE];         // combined0, NHWC
__device__ __align__(16) float    g_qkv [(size_t)NPIX*384]; // per-PIXEL qkv
__device__ __align__(16) float    g_o2  [(size_t)NTOK*128];
__device__ __align__(16) float    g_att [(size_t)NTOK*128];
__device__ __align__(16) uint32_t g_wt  [73728];            // tf32 weights [seg][pos][ic][oc]
__device__ float cbias1[64];    // [br*32 + oc]
__device__ float cbias2[128];   // [br*64 + oc]

// ---------------------------------------------------------------------------
// tf32 helpers
// ---------------------------------------------------------------------------
__device__ __forceinline__ uint32_t f2tf(float f) {
    uint32_t u;
    asm("cvt.rna.tf32.f32 %0, %1;" : "=r"(u) : "f"(f));
    return u;
}

__device__ __forceinline__ void mma_tf32(float* d, const uint32_t* a, const uint32_t* b) {
    asm volatile(
        "mma.sync.aligned.m16n8k8.row.col.f32.tf32.tf32.f32 "
        "{%0,%1,%2,%3}, {%4,%5,%6,%7}, {%8,%9}, {%0,%1,%2,%3};\n"
        : "+f"(d[0]), "+f"(d[1]), "+f"(d[2]), "+f"(d[3])
        : "r"(a[0]), "r"(a[1]), "r"(a[2]), "r"(a[3]), "r"(b[0]), "r"(b[1]));
}

// ---------------------------------------------------------------------------
// Weight pre-transpose: w[oc][ic][3x3] -> g_wt[seg][pos][ic][oc] (tf32 bits)
// ---------------------------------------------------------------------------
__global__ void wt_transpose_kernel(const float* __restrict__ mw1, const float* __restrict__ aw1,
                                    const float* __restrict__ mw2, const float* __restrict__ aw2)
{
    int flat = blockIdx.x * 256 + threadIdx.x;   // 0..73727
    int seg = flat / 18432;
    int r   = flat - seg * 18432;
    int pos = r / 2048;
    int r2  = r - pos * 2048;
    float v;
    if (seg < 2) {
        int ic = r2 >> 5, oc = r2 & 31;
        const float* w = seg ? aw1 : mw1;        // [32][64][9]
        v = w[oc * 576 + ic * 9 + pos];
    } else {
        int ic = r2 >> 6, oc = r2 & 63;
        const float* w = (seg == 3) ? aw2 : mw2; // [64][32][9]
        v = w[oc * 288 + ic * 9 + pos];
    }
    g_wt[flat] = f2tf(v);
}

__global__ void wt_bias_kernel(const float* __restrict__ mb1, const float* __restrict__ ab1,
                               const float* __restrict__ mb2, const float* __restrict__ ab2)
{
    int t = threadIdx.x;           // 0..191
    if (t < 32)        cbias1[t]      = mb1[t];
    else if (t < 64)   cbias1[t]      = ab1[t - 32];
    else if (t < 128)  cbias2[t - 64] = mb2[t - 64];
    else               cbias2[t - 64] = ab2[t - 128];
}

// ---------------------------------------------------------------------------
// Implicit-GEMM tf32 conv (3x3, SAME).  8x8 px tile, 128 thr, N=Cout, K=Cin*9.
// ---------------------------------------------------------------------------
template<bool FIRST>
__global__ __launch_bounds__(128)
void conv_mma(const float* __restrict__ vin)
{
    constexpr int CIN   = FIRST ? 64 : 32;
    constexpr int COUT  = FIRST ? 32 : 64;
    constexpr int COUTP = FIRST ? 40 : 72;
    constexpr int NF    = COUT / 8;
    constexpr int PLANE = 104;
    constexpr int SHWORDS = FIRST ? (CIN * PLANE) : 4352;

    __shared__ uint32_t shbuf[SHWORDS];
    __shared__ uint32_t Bs[2][CIN * COUTP];

    int tid  = threadIdx.x;
    int lane = tid & 31;
    int warp = tid >> 5;
    int g = lane >> 2, c = lane & 3;

    int x0 = blockIdx.x * 8;
    int y0 = blockIdx.y * 8;
    int z  = blockIdx.z;
    int b  = z >> 1, br = z & 1;

    const uint32_t* wt = g_wt + (FIRST ? 0 : 36864) + br * 18432;

    const float* inB = FIRST ? (vin + (size_t)(b * 128 + br * 64) * HW)
                             : (g_mid + (size_t)(b * 64 + br * 32) * HW);

    for (int idx = tid; idx < CIN * 100; idx += 128) {
        int ic = idx / 100;
        int r  = idx - ic * 100;
        int iy = r / 10, ix = r - iy * 10;
        int gy = y0 + iy - 1, gx = x0 + ix - 1;
        float v = 0.f;
        if (gy >= 0 && gy < 128 && gx >= 0 && gx < 128)
            v = inB[(size_t)ic * HW + gy * 128 + gx];
        shbuf[ic * PLANE + iy * 10 + ix] = f2tf(v);
    }

    float acc[NF][4];
#pragma unroll
    for (int nt = 0; nt < NF; nt++)
#pragma unroll
        for (int r = 0; r < 4; r++) acc[nt][r] = 0.f;

#pragma unroll
    for (int pos = 0; pos < 9; pos++) {
        int ky = pos / 3, kx = pos - ky * 3;
        uint32_t* B = Bs[pos & 1];
        {
            const uint4* src = reinterpret_cast<const uint4*>(wt + pos * CIN * COUT);
#pragma unroll
            for (int i4 = 0; i4 < (CIN * COUT / 4) / 128; i4++) {
                int id = tid + i4 * 128;
                uint4 v = src[id];
                int idx = id * 4;
                int ic = idx / COUT, oc = idx % COUT;
                *reinterpret_cast<uint4*>(&B[ic * COUTP + oc]) = v;
            }
        }
        __syncthreads();

        int abase = (warp * 2 + ky) * 10 + g + kx;
#pragma unroll
        for (int kk = 0; kk < CIN / 8; kk++) {
            int ic0 = kk * 8 + c;
            uint32_t a[4];
            a[0] = shbuf[ic0 * PLANE + abase];
            a[1] = shbuf[ic0 * PLANE + abase + 10];
            a[2] = shbuf[(ic0 + 4) * PLANE + abase];
            a[3] = shbuf[(ic0 + 4) * PLANE + abase + 10];
#pragma unroll
            for (int nt = 0; nt < NF; nt++) {
                uint32_t bb[2];
                bb[0] = B[ic0 * COUTP + nt * 8 + g];
                bb[1] = B[(ic0 + 4) * COUTP + nt * 8 + g];
                mma_tf32(acc[nt], a, bb);
            }
        }
        __syncthreads();
    }

    if (FIRST) {
        int cb = b * 64 + br * 32;
        int rowA = (y0 + warp * 2) * 128 + x0 + g;
        int rowB = rowA + 128;
#pragma unroll
        for (int nt = 0; nt < NF; nt++) {
            int oc0 = nt * 8 + c * 2;
            float b0 = cbias1[br * 32 + oc0];
            float b1 = cbias1[br * 32 + oc0 + 1];
            g_mid[(size_t)(cb + oc0    ) * HW + rowA] = fmaxf(acc[nt][0] + b0, 0.f);
            g_mid[(size_t)(cb + oc0 + 1) * HW + rowA] = fmaxf(acc[nt][1] + b1, 0.f);
            g_mid[(size_t)(cb + oc0    ) * HW + rowB] = fmaxf(acc[nt][2] + b0, 0.f);
            g_mid[(size_t)(cb + oc0 + 1) * HW + rowB] = fmaxf(acc[nt][3] + b1, 0.f);
        }
    } else {
        __syncthreads();
        float* sout = reinterpret_cast<float*>(shbuf);
        int pA = warp * 16 + g;
#pragma unroll
        for (int nt = 0; nt < NF; nt++) {
            int oc0 = nt * 8 + c * 2;
            float b0 = cbias2[br * 64 + oc0];
            float b1 = cbias2[br * 64 + oc0 + 1];
            sout[pA * 68 + oc0]           = acc[nt][0] + b0;
            sout[pA * 68 + oc0 + 1]       = acc[nt][1] + b1;
            sout[(pA + 8) * 68 + oc0]     = acc[nt][2] + b0;
            sout[(pA + 8) * 68 + oc0 + 1] = acc[nt][3] + b1;
        }
        __syncthreads();
        for (int f = tid; f < 1024; f += 128) {
            int p = f >> 4, q = f & 15;
            float4 v = make_float4(sout[p * 68 + q * 4],     sout[p * 68 + q * 4 + 1],
                                   sout[p * 68 + q * 4 + 2], sout[p * 68 + q * 4 + 3]);
            int y = y0 + (p >> 3), x = x0 + (p & 7);
            *reinterpret_cast<float4*>(
                g_nhwc + ((size_t)(b * 128 + y) * 128 + x) * 128 + br * 64 + q * 4) = v;
        }
    }
}

// ---------------------------------------------------------------------------
// tf32 tensor-core GEMM: C[M x N] = A[M x 128] * Wt[N x 128]^T + bias.
// ---------------------------------------------------------------------------
__global__ __launch_bounds__(256)
void gemm_tf32_kernel(const float* __restrict__ A, const float* __restrict__ Wt,
                      const float* __restrict__ bias, float* __restrict__ C, int N)
{
    __shared__ uint32_t As[32][136];
    __shared__ uint32_t Bs[32][136];

    int tid  = threadIdx.x;
    int lane = tid & 31;
    int wid  = tid >> 5;
    int wm = wid & 1;
    int wn = wid >> 1;
    int m0 = blockIdx.y * 128;
    int n0 = blockIdx.x * 128;

    float acc[4][4][4];
#pragma unroll
    for (int mt = 0; mt < 4; mt++)
#pragma unroll
        for (int nt = 0; nt < 4; nt++)
#pragma unroll
            for (int r = 0; r < 4; r++) acc[mt][nt][r] = 0.f;

    int q = tid & 7;
    const float* arow[4];
    const float* brow[4];
    int rowIdx[4];
#pragma unroll
    for (int s = 0; s < 4; s++) {
        int row = (tid >> 3) + 32 * s;
        rowIdx[s] = row;
        arow[s] = A + (size_t)(m0 + row) * 128;
        brow[s] = Wt + (size_t)(n0 + row) * 128;
    }

    for (int k0 = 0; k0 < 128; k0 += 32) {
        __syncthreads();
#pragma unroll
        for (int s = 0; s < 4; s++) {
#pragma unroll
            for (int c = 0; c < 4; c++) {
                int k = q + 8 * c;
                As[k][rowIdx[s]] = f2tf(arow[s][k0 + k]);
                Bs[k][rowIdx[s]] = f2tf(brow[s][k0 + k]);
            }
        }
        __syncthreads();

#pragma unroll
        for (int kk = 0; kk < 4; kk++) {
            int c = lane & 3;
            int g = lane >> 2;
            uint32_t a[4][4], b[4][2];
#pragma unroll
            for (int mt = 0; mt < 4; mt++) {
                int r = wm * 64 + mt * 16 + g;
                a[mt][0] = As[kk * 8 + c    ][r];
                a[mt][1] = As[kk * 8 + c    ][r + 8];
                a[mt][2] = As[kk * 8 + c + 4][r];
                a[mt][3] = As[kk * 8 + c + 4][r + 8];
            }
#pragma unroll
            for (int nt = 0; nt < 4; nt++) {
                int n = wn * 32 + nt * 8 + g;
                b[nt][0] = Bs[kk * 8 + c    ][n];
                b[nt][1] = Bs[kk * 8 + c + 4][n];
            }
#pragma unroll
            for (int mt = 0; mt < 4; mt++)
#pragma unroll
                for (int nt = 0; nt < 4; nt++)
                    mma_tf32(acc[mt][nt], a[mt], b[nt]);
        }
    }

    int g  = lane >> 2;
    int c2 = (lane & 3) * 2;
#pragma unroll
    for (int mt = 0; mt < 4; mt++) {
        int row = m0 + wm * 64 + mt * 16 + g;
#pragma unroll
        for (int nt = 0; nt < 4; nt++) {
            int col = n0 + wn * 32 + nt * 8 + c2;
            float b0 = __ldg(bias + col);
            float b1 = __ldg(bias + col + 1);
            float2 v0 = make_float2(acc[mt][nt][0] + b0, acc[mt][nt][1] + b1);
            float2 v1 = make_float2(acc[mt][nt][2] + b0, acc[mt][nt][3] + b1);
            *reinterpret_cast<float2*>(C + (size_t)row * N + col)       = v0;
            *reinterpret_cast<float2*>(C + (size_t)(row + 8) * N + col) = v1;
        }
    }
}

// ---------------------------------------------------------------------------
// Attention core (tensor cores, coalesced I/O, per-pixel qkv gather).
// ---------------------------------------------------------------------------
__global__ __launch_bounds__(128)
void attn_kernel()
{
    __shared__ uint32_t qsT[32][73];
    __shared__ uint32_t ksT[32][73];
    __shared__ uint32_t vs [64][40];
    __shared__ float    st [64][68];
    __shared__ float    smx[128];
    __shared__ float    ssum[128];

    int bx   = blockIdx.x;
    int head = bx & 3;
    int wb   = bx >> 2;
    int rowBase = wb * 64;          // token rows for O output
    int b   = wb & 3;
    int win = wb >> 2;
    int hi  = win / NH_;
    int wi  = win - hi * NH_;
    int tid  = threadIdx.x;
    int lane = tid & 31;
    int warp = tid >> 5;
    const float scale = 0.17677669529663687f;  // 1/sqrt(32)

#pragma unroll
    for (int s = 0; s < 4; s++) {
        int idx = tid + s * 128;
        int l   = idx >> 3;
        int d   = (idx & 7) * 4;
        int h   = hi * 4 + (l >> 3);
        int w   = wi * 4 + (l & 7);
        const float* p = g_qkv + ((size_t)((b * 128 + h) * 128 + w)) * 384 + head * 32 + d;
        float4 qv = *reinterpret_cast<const float4*>(p);
        float4 kv = *reinterpret_cast<const float4*>(p + 128);
        float4 vv = *reinterpret_cast<const float4*>(p + 256);
        qsT[d + 0][l] = f2tf(qv.x * scale);
        qsT[d + 1][l] = f2tf(qv.y * scale);
        qsT[d + 2][l] = f2tf(qv.z * scale);
        qsT[d + 3][l] = f2tf(qv.w * scale);
        ksT[d + 0][l] = f2tf(kv.x);
        ksT[d + 1][l] = f2tf(kv.y);
        ksT[d + 2][l] = f2tf(kv.z);
        ksT[d + 3][l] = f2tf(kv.w);
        uint4 vt;
        vt.x = f2tf(vv.x); vt.y = f2tf(vv.y);
        vt.z = f2tf(vv.z); vt.w = f2tf(vv.w);
        *reinterpret_cast<uint4*>(&vs[l][d]) = vt;
    }
    __syncthreads();

    int g = lane >> 2, c = lane & 3;
    int lbase = warp * 16;

    {
        float sacc[8][4];
#pragma unroll
        for (int nt = 0; nt < 8; nt++)
#pragma unroll
            for (int r = 0; r < 4; r++) sacc[nt][r] = 0.f;

#pragma unroll
        for (int kk = 0; kk < 4; kk++) {
            uint32_t a[4];
            a[0] = qsT[kk * 8 + c    ][lbase + g];
            a[1] = qsT[kk * 8 + c    ][lbase + g + 8];
            a[2] = qsT[kk * 8 + c + 4][lbase + g];
            a[3] = qsT[kk * 8 + c + 4][lbase + g + 8];
#pragma unroll
            for (int nt = 0; nt < 8; nt++) {
                uint32_t b2[2];
                b2[0] = ksT[kk * 8 + c    ][nt * 8 + g];
                b2[1] = ksT[kk * 8 + c + 4][nt * 8 + g];
                mma_tf32(sacc[nt], a, b2);
            }
        }
#pragma unroll
        for (int nt = 0; nt < 8; nt++) {
            int m = nt * 8 + c * 2;
            st[m    ][lbase + g]     = sacc[nt][0];
            st[m + 1][lbase + g]     = sacc[nt][1];
            st[m    ][lbase + g + 8] = sacc[nt][2];
            st[m + 1][lbase + g + 8] = sacc[nt][3];
        }
    }
    __syncthreads();

    {
        int l     = tid & 63;
        int part  = tid >> 6;
        int mbase = part * 32;
        float mx = -1e30f;
#pragma unroll
        for (int i = 0; i < 32; i++) mx = fmaxf(mx, st[mbase + i][l]);
        smx[part * 64 + l] = mx;
        __syncthreads();
        mx = fmaxf(smx[l], smx[64 + l]);
        float s = 0.f;
        float ev[32];
#pragma unroll
        for (int i = 0; i < 32; i++) {
            float e = __expf(st[mbase + i][l] - mx);
            ev[i] = e;
            s += e;
        }
        ssum[part * 64 + l] = s;
        __syncthreads();
        float inv = 1.f / (ssum[l] + ssum[64 + l]);
#pragma unroll
        for (int i = 0; i < 32; i++)
            st[mbase + i][l] = __uint_as_float(f2tf(ev[i] * inv));
    }
    __syncthreads();

    float oacc[4][4];
#pragma unroll
    for (int nt = 0; nt < 4; nt++)
#pragma unroll
        for (int r = 0; r < 4; r++) oacc[nt][r] = 0.f;

#pragma unroll
    for (int kk = 0; kk < 8; kk++) {
        uint32_t a[4];
        a[0] = __float_as_uint(st[kk * 8 + c    ][lbase + g]);
        a[1] = __float_as_uint(st[kk * 8 + c    ][lbase + g + 8]);
        a[2] = __float_as_uint(st[kk * 8 + c + 4][lbase + g]);
        a[3] = __float_as_uint(st[kk * 8 + c + 4][lbase + g + 8]);
#pragma unroll
        for (int nt = 0; nt < 4; nt++) {
            uint32_t b2[2];
            b2[0] = vs[kk * 8 + c    ][nt * 8 + g];
            b2[1] = vs[kk * 8 + c + 4][nt * 8 + g];
            mma_tf32(oacc[nt], a, b2);
        }
    }
    __syncthreads();

    {
        int c2 = c * 2;
#pragma unroll
        for (int nt = 0; nt < 4; nt++) {
            int d = nt * 8 + c2;
            st[lbase + g    ][d]     = oacc[nt][0];
            st[lbase + g    ][d + 1] = oacc[nt][1];
            st[lbase + g + 8][d]     = oacc[nt][2];
            st[lbase + g + 8][d + 1] = oacc[nt][3];
        }
    }
    __syncthreads();

#pragma unroll
    for (int s = 0; s < 2; s++) {
        int idx = tid + s * 128;
        int row = idx >> 2;
        int d   = (idx & 3) * 8;
        float4 v0 = make_float4(st[row][d], st[row][d+1], st[row][d+2], st[row][d+3]);
        float4 v1 = make_float4(st[row][d+4], st[row][d+5], st[row][d+6], st[row][d+7]);
        float* p = g_o2 + (size_t)(rowBase + row) * 128 + head * 32 + d;
        reinterpret_cast<float4*>(p)[0] = v0;
        reinterpret_cast<float4*>(p)[1] = v1;
    }
}

// ---------------------------------------------------------------------------
// Blend (analytic scan, high-MLP fold) + 1x1 conv + sigmoid gate + residual.
// Each pixel is covered by <=2 windows per dim (WS=8, STR=4): exactly 4
// clamped loads issued up front, predicated fold (warp-uniform predicates).
// ---------------------------------------------------------------------------
__global__ void blend_kernel(const float* __restrict__ fcw, const float* __restrict__ fcb,
                             const float* __restrict__ vf, float* __restrict__ out)
{
    __shared__ float enh[32][129];
    __shared__ float fw [32][65];
    __shared__ float fcs[128][76];
    __shared__ float fbs[64];

    int wc = blockIdx.x;     // 0..3
    int h  = blockIdx.y;     // 0..127
    int b  = blockIdx.z;     // 0..3
    int w0 = wc * 32;
    int tid = threadIdx.x;

    for (int idx = tid; idx < 64 * 128; idx += 256) {
        int c = idx >> 7, e = idx & 127;
        fcs[e][c] = fcw[idx];
    }
    if (tid < 64) fbs[tid] = fcb[tid];

    int hiLo = max(0, (h - 4) >> 2);
    int hiHi = min(NH_ - 1, h >> 2);
    bool haveH = (hiHi > hiLo);
    int lrLo = (h - hiLo * 4) * 8;
    int lrHi = (h - hiHi * 4) * 8;

#pragma unroll 4
    for (int s = 0; s < 16; s++) {
        int idx = tid + s * 256;
        int px = idx >> 7;
        int e  = idx & 127;
        int wpix = w0 + px;
        int wiLo = max(0, (wpix - 4) >> 2);
        int wiHi = min(NH_ - 1, wpix >> 2);
        bool haveW = (wiHi > wiLo);

        // issue all 5 loads up front (clamped -> always valid addresses)
        float c0 = g_nhwc[((size_t)(b * HH + h) * WWID + wpix) * EE + e];
        size_t r00 = (size_t)(((hiLo * NH_ + wiLo) * 4 + b) * 64 + lrLo + (wpix - wiLo * 4)) * 128 + e;
        size_t r01 = (size_t)(((hiLo * NH_ + wiHi) * 4 + b) * 64 + lrLo + (wpix - wiHi * 4)) * 128 + e;
        size_t r10 = (size_t)(((hiHi * NH_ + wiLo) * 4 + b) * 64 + lrHi + (wpix - wiLo * 4)) * 128 + e;
        size_t r11 = (size_t)(((hiHi * NH_ + wiHi) * 4 + b) * 64 + lrHi + (wpix - wiHi * 4)) * 128 + e;
        float a00 = __ldg(g_att + r00);
        float a01 = __ldg(g_att + r01);
        float a10 = __ldg(g_att + r10);
        float a11 = __ldg(g_att + r11);

        // ordered fold (window index ascending), predicated
        float val = c0 * 0.7f + 0.3f * a00;
        if (haveW) val = val * 0.7f + 0.3f * a01;
        if (haveH) {
            val = val * 0.7f + 0.3f * a10;
            if (haveW) val = val * 0.7f + 0.3f * a11;
        }
        enh[px][e] = val;
    }
    __syncthreads();

    {
        int px = tid >> 3;
        int cg = tid & 7;
        float acc[8];
#pragma unroll
        for (int j = 0; j < 8; j++) acc[j] = fbs[cg * 8 + j];
#pragma unroll 4
        for (int e = 0; e < 128; e++) {
            float a = enh[px][e];
            const float4* bp = reinterpret_cast<const float4*>(&fcs[e][cg * 8]);
            float4 b0 = bp[0];
            float4 b1 = bp[1];
            acc[0] += a * b0.x; acc[1] += a * b0.y;
            acc[2] += a * b0.z; acc[3] += a * b0.w;
            acc[4] += a * b1.x; acc[5] += a * b1.y;
            acc[6] += a * b1.z; acc[7] += a * b1.w;
        }
#pragma unroll
        for (int j = 0; j < 8; j++)
            fw[px][cg * 8 + j] = 1.f / (1.f + __expf(-acc[j]));
    }
    __syncthreads();

    for (int s = 0; s < 16; s++) {
        int idx = tid + s * 256;
        int px = idx & 31;
        int ch = idx >> 5;
        size_t off = ((size_t)(b * 128 + ch) * HH + h) * WWID + w0 + px;
        out[off] = enh[px][ch] * fw[px][ch & 63] + vf[off];
    }
}

// ---------------------------------------------------------------------------
// Launch
// ---------------------------------------------------------------------------
extern "C" void kernel_launch(void* const* d_in, const int* in_sizes, int n_in,
                              void* d_out, int out_size)
{
    const float* vf    = (const float*)d_in[0];
    const float* mw1   = (const float*)d_in[1];
    const float* mb1   = (const float*)d_in[2];
    const float* mw2   = (const float*)d_in[3];
    const float* mb2   = (const float*)d_in[4];
    const float* aw1   = (const float*)d_in[5];
    const float* ab1   = (const float*)d_in[6];
    const float* aw2   = (const float*)d_in[7];
    const float* ab2   = (const float*)d_in[8];
    const float* ipw   = (const float*)d_in[9];   // [384,128]
    const float* ipb   = (const float*)d_in[10];
    const float* opw   = (const float*)d_in[11];  // [128,128]
    const float* opb   = (const float*)d_in[12];
    const float* fcw   = (const float*)d_in[13];  // [64,128]
    const float* fcb   = (const float*)d_in[14];
    float* out = (float*)d_out;

    void *pnhwc, *pqkv, *po2, *patt;
    cudaGetSymbolAddress(&pnhwc, g_nhwc);
    cudaGetSymbolAddress(&pqkv, g_qkv);
    cudaGetSymbolAddress(&po2,  g_o2);
    cudaGetSymbolAddress(&patt, g_att);

    // weight/bias pre-transpose (tiny)
    wt_transpose_kernel<<<288, 256>>>(mw1, aw1, mw2, aw2);
    wt_bias_kernel<<<1, 192>>>(mb1, ab1, mb2, ab2);

    // convs: implicit-GEMM tf32 with pre-transposed weights
    conv_mma<true ><<<dim3(16, 16, 8), 128>>>(vf);
    conv_mma<false><<<dim3(16, 16, 8), 128>>>(nullptr);

    // QKV per PIXEL: g_nhwc [65536,128] x [384,128]^T -> g_qkv
    gemm_tf32_kernel<<<dim3(3, NPIX / 128), 256>>>(
        (const float*)pnhwc, ipw, ipb, (float*)pqkv, 384);

    attn_kernel<<<NWB * 4, 128>>>();

    // out-proj: g_o2 [NTOK,128] x [128,128]^T -> g_att
    gemm_tf32_kernel<<<dim3(1, NTOK / 128), 256>>>(
        (const float*)po2, opw, opb, (float*)patt, 128);

    blend_kernel<<<dim3(4, HH, BB), 256>>>(fcw, fcb, vf, out);
}